// round 9
// baseline (speedup 1.0000x reference)
#include <cuda_runtime.h>
#include <math.h>
#include <stdint.h>

// ---------------- problem constants ----------------
#define Bsz 4
#define Nn  1025
#define Cc  768
#define Hh  12
#define Dh  64
#define BH  (Bsz*Hh)           // 48
#define SLD 1028               // padded row stride for S
#define KLD 1028               // padded row stride for keep mask (16B-aligned rows)
#define SB  ((size_t)Nn*SLD)
#define KSEL 256

// ---------------- scratch (device globals; allocs forbidden) ----------------
__device__ float g_qkv[(size_t)Bsz*Nn*3*Cc];
__device__ float g_S  [(size_t)BH*Nn*SLD];
__device__ float g_ctx[(size_t)Bsz*Nn*Cc];
__device__ float g_patch[BH*Nn];
__device__ float g_gucb[Bsz*(Nn-1)];
__device__ float g_keep[Bsz*KLD];
__device__ float g_cnt[Nn];

// ---------------- tf32 helpers ----------------
__device__ __forceinline__ uint32_t f2tf(float x){
    uint32_t r; asm("cvt.rna.tf32.f32 %0, %1;" : "=r"(r) : "f"(x)); return r;
}
__device__ __forceinline__ void mma8(float* d, const uint32_t* a, const uint32_t* b){
    asm volatile("mma.sync.aligned.m16n8k8.row.col.f32.tf32.tf32.f32 "
        "{%0,%1,%2,%3}, {%4,%5,%6,%7}, {%8,%9}, {%0,%1,%2,%3};"
        : "+f"(d[0]), "+f"(d[1]), "+f"(d[2]), "+f"(d[3])
        : "r"(a[0]), "r"(a[1]), "r"(a[2]), "r"(a[3]), "r"(b[0]), "r"(b[1]));
}

// =====================================================================
// mma_gemm_nn: C[M,N] = A[M,K] @ B[K,N] (+bias).  tf32 tensor cores.
// Block tile 128x128, BK=16, 8 warps (4m x 2n), warp tile 32m x 64n.
// =====================================================================
template<bool BIAS>
__global__ __launch_bounds__(256,1)
void mma_gemm_nn(const float* __restrict__ A, const float* __restrict__ B,
                 const float* __restrict__ bias, float* __restrict__ C,
                 int M, int N, int K, int lda, int ldb, int ldc)
{
    __shared__ uint32_t As[2][16][136];
    __shared__ uint32_t Bs[2][16][136];
    const int tid = threadIdx.x, lane = tid & 31, warp = tid >> 5;
    const int wm = warp & 3;
    const int wN = warp >> 2;                      // 0..1
    const int m0 = blockIdx.y*128, n0 = blockIdx.x*128;

    const int ar = tid >> 2, ak = (tid & 3) << 2;
    const bool aok0 = (m0 + ar)      < M;
    const bool aok1 = (m0 + ar + 64) < M;
    const float* Ap0 = A + (size_t)(m0+ar)*lda + ak;
    const float* Ap1 = A + (size_t)(m0+ar+64)*lda + ak;
    const int bk = tid >> 5, bn = (tid & 31) << 2;
    const float* Bp0 = B + (size_t)bk*ldb + n0 + bn;
    const float* Bp1 = B + (size_t)(bk+8)*ldb + n0 + bn;

    const float4 z4 = make_float4(0.f,0.f,0.f,0.f);
    float4 a0 = aok0 ? *(const float4*)Ap0 : z4;
    float4 a1 = aok1 ? *(const float4*)Ap1 : z4;
    float4 b0 = *(const float4*)Bp0;
    float4 b1 = *(const float4*)Bp1;

    auto stA = [&](int buf, const float4& v0, const float4& v1){
        As[buf][ak+0][ar]=f2tf(v0.x); As[buf][ak+1][ar]=f2tf(v0.y);
        As[buf][ak+2][ar]=f2tf(v0.z); As[buf][ak+3][ar]=f2tf(v0.w);
        As[buf][ak+0][ar+64]=f2tf(v1.x); As[buf][ak+1][ar+64]=f2tf(v1.y);
        As[buf][ak+2][ar+64]=f2tf(v1.z); As[buf][ak+3][ar+64]=f2tf(v1.w);
    };
    auto stB = [&](int buf, const float4& v0, const float4& v1){
        *(uint4*)&Bs[buf][bk  ][bn] = make_uint4(f2tf(v0.x),f2tf(v0.y),f2tf(v0.z),f2tf(v0.w));
        *(uint4*)&Bs[buf][bk+8][bn] = make_uint4(f2tf(v1.x),f2tf(v1.y),f2tf(v1.z),f2tf(v1.w));
    };

    stA(0,a0,a1); stB(0,b0,b1); __syncthreads();

    float acc[2][8][4];
    #pragma unroll
    for (int i=0;i<2;i++)
        #pragma unroll
        for (int j=0;j<8;j++)
            #pragma unroll
            for (int q=0;q<4;q++) acc[i][j][q]=0.f;

    const int nk = K >> 4;
    for (int t=0;t<nk;t++){
        const int cur = t & 1;
        if (t+1<nk){
            a0 = aok0 ? *(const float4*)(Ap0 + (t+1)*16) : z4;
            a1 = aok1 ? *(const float4*)(Ap1 + (t+1)*16) : z4;
            b0 = *(const float4*)(Bp0 + (size_t)(t+1)*16*ldb);
            b1 = *(const float4*)(Bp1 + (size_t)(t+1)*16*ldb);
        }
        #pragma unroll
        for (int ks=0;ks<2;ks++){
            const int kb = ks*8;
            uint32_t af[2][4], bf[8][2];
            #pragma unroll
            for (int mt=0;mt<2;mt++){
                const int r = wm*32 + mt*16 + (lane>>2);
                af[mt][0] = As[cur][kb+(lane&3)  ][r];
                af[mt][1] = As[cur][kb+(lane&3)  ][r+8];
                af[mt][2] = As[cur][kb+(lane&3)+4][r];
                af[mt][3] = As[cur][kb+(lane&3)+4][r+8];
            }
            #pragma unroll
            for (int nt=0;nt<8;nt++){
                const int c = wN*64 + nt*8 + (lane>>2);
                bf[nt][0] = Bs[cur][kb+(lane&3)  ][c];
                bf[nt][1] = Bs[cur][kb+(lane&3)+4][c];
            }
            #pragma unroll
            for (int mt=0;mt<2;mt++)
                #pragma unroll
                for (int nt=0;nt<8;nt++) mma8(acc[mt][nt], af[mt], bf[nt]);
        }
        if (t+1<nk){ const int nxt = cur^1; stA(nxt,a0,a1); stB(nxt,b0,b1); }
        __syncthreads();
    }

    #pragma unroll
    for (int mt=0;mt<2;mt++){
        const int r0 = m0 + wm*32 + mt*16 + (lane>>2);
        #pragma unroll
        for (int nt=0;nt<8;nt++){
            const int gc = n0 + wN*64 + nt*8 + (lane&3)*2;
            float bx=0.f, by=0.f;
            if (BIAS){ bx = bias[gc]; by = bias[gc+1]; }
            if (r0 < M){
                float2 v; v.x = acc[mt][nt][0]+bx; v.y = acc[mt][nt][1]+by;
                *(float2*)&C[(size_t)r0*ldc + gc] = v;
            }
            if (r0+8 < M){
                float2 v; v.x = acc[mt][nt][2]+bx; v.y = acc[mt][nt][3]+by;
                *(float2*)&C[(size_t)(r0+8)*ldc + gc] = v;
            }
        }
    }
}

// =====================================================================
// mma_gemm_qk: S[bh] = 0.125 * Q @ K^T.  Operand rows stride 3*Cc.
// =====================================================================
__global__ __launch_bounds__(256,1)
void mma_gemm_qk(const float* __restrict__ QKV, float* __restrict__ S)
{
    const int bh = blockIdx.z, b = bh / Hh, h = bh % Hh;
    const float* Q  = QKV + (size_t)b*Nn*3*Cc + (size_t)h*Dh;
    const float* Km = Q + Cc;
    float* Cs = S + (size_t)bh * SB;

    __shared__ uint32_t As[2][16][136];
    __shared__ uint32_t Bs[2][16][136];
    const int tid = threadIdx.x, lane = tid & 31, warp = tid >> 5;
    const int wm = warp & 3, wN = warp >> 2;
    const int m0 = blockIdx.y*128, n0 = blockIdx.x*128;

    const int ar = tid >> 2, ak = (tid & 3) << 2;
    const bool aok0 = (m0 + ar)      < Nn;
    const bool aok1 = (m0 + ar + 64) < Nn;
    const bool bok0 = (n0 + ar)      < Nn;
    const bool bok1 = (n0 + ar + 64) < Nn;
    const float* Ap0 = Q  + (size_t)(m0+ar)*(3*Cc) + ak;
    const float* Ap1 = Q  + (size_t)(m0+ar+64)*(3*Cc) + ak;
    const float* Bp0 = Km + (size_t)(n0+ar)*(3*Cc) + ak;
    const float* Bp1 = Km + (size_t)(n0+ar+64)*(3*Cc) + ak;

    const float4 z4 = make_float4(0.f,0.f,0.f,0.f);
    float4 a0 = aok0 ? *(const float4*)Ap0 : z4;
    float4 a1 = aok1 ? *(const float4*)Ap1 : z4;
    float4 b0 = bok0 ? *(const float4*)Bp0 : z4;
    float4 b1 = bok1 ? *(const float4*)Bp1 : z4;

    auto stT = [&](uint32_t (*dst)[136], const float4& v0, const float4& v1){
        dst[ak+0][ar]=f2tf(v0.x); dst[ak+1][ar]=f2tf(v0.y);
        dst[ak+2][ar]=f2tf(v0.z); dst[ak+3][ar]=f2tf(v0.w);
        dst[ak+0][ar+64]=f2tf(v1.x); dst[ak+1][ar+64]=f2tf(v1.y);
        dst[ak+2][ar+64]=f2tf(v1.z); dst[ak+3][ar+64]=f2tf(v1.w);
    };

    stT(As[0],a0,a1); stT(Bs[0],b0,b1); __syncthreads();

    float acc[2][8][4];
    #pragma unroll
    for (int i=0;i<2;i++)
        #pragma unroll
        for (int j=0;j<8;j++)
            #pragma unroll
            for (int q=0;q<4;q++) acc[i][j][q]=0.f;

    const int nk = Dh >> 4;   // 4
    for (int t=0;t<nk;t++){
        const int cur = t & 1;
        if (t+1<nk){
            a0 = aok0 ? *(const float4*)(Ap0 + (t+1)*16) : z4;
            a1 = aok1 ? *(const float4*)(Ap1 + (t+1)*16) : z4;
            b0 = bok0 ? *(const float4*)(Bp0 + (t+1)*16) : z4;
            b1 = bok1 ? *(const float4*)(Bp1 + (t+1)*16) : z4;
        }
        #pragma unroll
        for (int ks=0;ks<2;ks++){
            const int kb = ks*8;
            uint32_t af[2][4], bf[8][2];
            #pragma unroll
            for (int mt=0;mt<2;mt++){
                const int r = wm*32 + mt*16 + (lane>>2);
                af[mt][0] = As[cur][kb+(lane&3)  ][r];
                af[mt][1] = As[cur][kb+(lane&3)  ][r+8];
                af[mt][2] = As[cur][kb+(lane&3)+4][r];
                af[mt][3] = As[cur][kb+(lane&3)+4][r+8];
            }
            #pragma unroll
            for (int nt=0;nt<8;nt++){
                const int c = wN*64 + nt*8 + (lane>>2);
                bf[nt][0] = Bs[cur][kb+(lane&3)  ][c];
                bf[nt][1] = Bs[cur][kb+(lane&3)+4][c];
            }
            #pragma unroll
            for (int mt=0;mt<2;mt++)
                #pragma unroll
                for (int nt=0;nt<8;nt++) mma8(acc[mt][nt], af[mt], bf[nt]);
        }
        if (t+1<nk){ const int nxt = cur^1; stT(As[nxt],a0,a1); stT(Bs[nxt],b0,b1); }
        __syncthreads();
    }

    const float alpha = 0.125f;
    #pragma unroll
    for (int mt=0;mt<2;mt++){
        const int r0 = m0 + wm*32 + mt*16 + (lane>>2);
        #pragma unroll
        for (int nt=0;nt<8;nt++){
            const int gc = n0 + wN*64 + nt*8 + (lane&3)*2;
            if (r0 < Nn){
                if (gc+1 < Nn){
                    float2 v; v.x=acc[mt][nt][0]*alpha; v.y=acc[mt][nt][1]*alpha;
                    *(float2*)&Cs[(size_t)r0*SLD + gc] = v;
                } else if (gc < Nn) Cs[(size_t)r0*SLD + gc] = acc[mt][nt][0]*alpha;
            }
            if (r0+8 < Nn){
                if (gc+1 < Nn){
                    float2 v; v.x=acc[mt][nt][2]*alpha; v.y=acc[mt][nt][3]*alpha;
                    *(float2*)&Cs[(size_t)(r0+8)*SLD + gc] = v;
                } else if (gc < Nn) Cs[(size_t)(r0+8)*SLD + gc] = acc[mt][nt][2]*alpha;
            }
        }
    }
}

// =====================================================================
// mma_gemm_ctx: fused prune-mask + renorm + (pruned @ V).
// =====================================================================
__global__ __launch_bounds__(256,1)
void mma_gemm_ctx(const float* __restrict__ S, const float* __restrict__ QKV,
                  float* __restrict__ ctx, const int* __restrict__ counter,
                  const int* __restrict__ enabled)
{
    const int bh = blockIdx.z, b = bh / Hh, h = bh % Hh;
    const bool prune = ((*enabled) != 0) && ((*counter) > 50);
    const float* Sp = S + (size_t)bh*SB;
    const float* V  = QKV + (size_t)b*Nn*3*Cc + 2*(size_t)Cc + (size_t)h*Dh;
    const float* kp = g_keep + (size_t)b*KLD;   // 16B-aligned rows
    float* Cp = ctx + (size_t)b*Nn*Cc + (size_t)h*Dh;

    __shared__ uint32_t As[2][16][136];
    __shared__ uint32_t Bs[2][16][72];
    __shared__ float zsh[128];

    const int tid = threadIdx.x, lane = tid & 31, warp = tid >> 5;
    const int wm = warp & 3, wN = warp >> 2;
    const int m0 = blockIdx.y*128;

    const int ar = tid >> 2, ak = (tid & 3) << 2;
    const int gm0 = m0 + ar, gm1 = m0 + ar + 64;
    const bool aok0 = gm0 < Nn, aok1 = gm1 < Nn;
    const float keep0 = (prune && aok0) ? kp[gm0] : 1.f;
    const float keep1 = (prune && aok1) ? kp[gm1] : 1.f;
    const float* Ap0 = Sp + (size_t)(aok0 ? gm0 : 0)*SLD;
    const float* Ap1 = Sp + (size_t)(aok1 ? gm1 : 0)*SLD;
    const int bk = tid >> 4, bn = (tid & 15) << 2;
    const float* Bp = V + (size_t)bk*(3*Cc) + bn;

    const float4 z4 = make_float4(0.f,0.f,0.f,0.f);
    float z0 = 0.f, z1 = 0.f;

    auto ldrow = [&](const float* rowp, float keepi, int k0, bool ok, float& zacc)->float4{
        float4 v = z4;
        if (ok){
            const int c = k0 + ak;
            if (c + 3 < Nn) v = *(const float4*)(rowp + c);
            else {
                if (c   < Nn) v.x = rowp[c];
                if (c+1 < Nn) v.y = rowp[c+1];
                if (c+2 < Nn) v.z = rowp[c+2];
                if (c+3 < Nn) v.w = rowp[c+3];
            }
            if (keepi < 0.5f){
                float4 kv = z4;
                if (c + 3 < Nn) kv = *(const float4*)(kp + c);   // kp rows 16B-aligned now
                else {
                    if (c   < Nn) kv.x = kp[c];
                    if (c+1 < Nn) kv.y = kp[c+1];
                    if (c+2 < Nn) kv.z = kp[c+2];
                    if (c+3 < Nn) kv.w = kp[c+3];
                }
                v.x*=kv.x; v.y*=kv.y; v.z*=kv.z; v.w*=kv.w;
            }
            zacc += (v.x+v.y)+(v.z+v.w);
        }
        return v;
    };
    auto ldB = [&](int k0)->float4{
        return (k0 + bk < Nn) ? *(const float4*)(Bp + (size_t)k0*(3*Cc)) : z4;
    };
    auto stA = [&](int buf, const float4& v0, const float4& v1){
        As[buf][ak+0][ar]=f2tf(v0.x); As[buf][ak+1][ar]=f2tf(v0.y);
        As[buf][ak+2][ar]=f2tf(v0.z); As[buf][ak+3][ar]=f2tf(v0.w);
        As[buf][ak+0][ar+64]=f2tf(v1.x); As[buf][ak+1][ar+64]=f2tf(v1.y);
        As[buf][ak+2][ar+64]=f2tf(v1.z); As[buf][ak+3][ar+64]=f2tf(v1.w);
    };
    auto stB = [&](int buf, const float4& v){
        *(uint4*)&Bs[buf][bk][bn] = make_uint4(f2tf(v.x),f2tf(v.y),f2tf(v.z),f2tf(v.w));
    };

    float4 a0 = ldrow(Ap0, keep0, 0, aok0, z0);
    float4 a1 = ldrow(Ap1, keep1, 0, aok1, z1);
    float4 bv = ldB(0);
    stA(0,a0,a1); stB(0,bv); __syncthreads();

    float acc[2][4][4];
    #pragma unroll
    for (int i=0;i<2;i++)
        #pragma unroll
        for (int j=0;j<4;j++)
            #pragma unroll
            for (int q=0;q<4;q++) acc[i][j][q]=0.f;

    const int nk = (Nn + 15) >> 4;   // 65
    for (int t=0;t<nk;t++){
        const int cur = t & 1;
        if (t+1<nk){
            a0 = ldrow(Ap0, keep0, (t+1)*16, aok0, z0);
            a1 = ldrow(Ap1, keep1, (t+1)*16, aok1, z1);
            bv = ldB((t+1)*16);
        }
        #pragma unroll
        for (int ks=0;ks<2;ks++){
            const int kb = ks*8;
            uint32_t af[2][4], bf[4][2];
            #pragma unroll
            for (int mt=0;mt<2;mt++){
                const int r = wm*32 + mt*16 + (lane>>2);
                af[mt][0] = As[cur][kb+(lane&3)  ][r];
                af[mt][1] = As[cur][kb+(lane&3)  ][r+8];
                af[mt][2] = As[cur][kb+(lane&3)+4][r];
                af[mt][3] = As[cur][kb+(lane&3)+4][r+8];
            }
            #pragma unroll
            for (int nt=0;nt<4;nt++){
                const int c = wN*32 + nt*8 + (lane>>2);
                bf[nt][0] = Bs[cur][kb+(lane&3)  ][c];
                bf[nt][1] = Bs[cur][kb+(lane&3)+4][c];
            }
            #pragma unroll
            for (int mt=0;mt<2;mt++)
                #pragma unroll
                for (int nt=0;nt<4;nt++) mma8(acc[mt][nt], af[mt], bf[nt]);
        }
        if (t+1<nk){ const int nxt = cur^1; stA(nxt,a0,a1); stB(nxt,bv); }
        __syncthreads();
    }

    z0 += __shfl_xor_sync(0xffffffffu, z0, 1);
    z0 += __shfl_xor_sync(0xffffffffu, z0, 2);
    z1 += __shfl_xor_sync(0xffffffffu, z1, 1);
    z1 += __shfl_xor_sync(0xffffffffu, z1, 2);
    if ((lane & 3) == 0){ zsh[ar] = z0; zsh[ar+64] = z1; }
    __syncthreads();

    #pragma unroll
    for (int mt=0;mt<2;mt++){
        const int lr = wm*32 + mt*16 + (lane>>2);
        const int r0 = m0 + lr;
        const float iz0 = prune ? 1.f/(zsh[lr]   + 1e-8f) : 1.f;
        const float iz1 = prune ? 1.f/(zsh[lr+8] + 1e-8f) : 1.f;
        #pragma unroll
        for (int nt=0;nt<4;nt++){
            const int gc = wN*32 + nt*8 + (lane&3)*2;
            if (r0 < Nn){
                float2 v; v.x=acc[mt][nt][0]*iz0; v.y=acc[mt][nt][1]*iz0;
                *(float2*)&Cp[(size_t)r0*Cc + gc] = v;
            }
            if (r0+8 < Nn){
                float2 v; v.x=acc[mt][nt][2]*iz1; v.y=acc[mt][nt][3]*iz1;
                *(float2*)&Cp[(size_t)(r0+8)*Cc + gc] = v;
            }
        }
    }
}

// ---------------- row softmax (vectorized) ----------------
__global__ __launch_bounds__(256)
void softmax_kernel(float* __restrict__ S)
{
    const int r = blockIdx.x;
    float* row = S + (size_t)(r / Nn)*SB + (size_t)(r % Nn)*SLD;
    const int t = threadIdx.x;
    __shared__ float red[256];

    float4 v = ((const float4*)row)[t];
    const float last = row[1024];
    float mx = fmaxf(fmaxf(v.x,v.y), fmaxf(v.z,v.w));
    mx = fmaxf(mx, last);
    red[t] = mx; __syncthreads();
    for (int s=128;s>0;s>>=1){ if (t<s) red[t]=fmaxf(red[t],red[t+s]); __syncthreads(); }
    mx = red[0]; __syncthreads();

    float4 e;
    e.x = __expf(v.x-mx); e.y = __expf(v.y-mx);
    e.z = __expf(v.z-mx); e.w = __expf(v.w-mx);
    const float el = __expf(last-mx);
    float sm = (e.x+e.y)+(e.z+e.w);
    if (t==0) sm += el;
    red[t] = sm; __syncthreads();
    for (int s=128;s>0;s>>=1){ if (t<s) red[t]+=red[t+s]; __syncthreads(); }
    const float inv = 1.f/red[0];
    e.x*=inv; e.y*=inv; e.z*=inv; e.w*=inv;
    ((float4*)row)[t] = e;
    if (t==0) row[1024] = el*inv;
}

// ---------------- zero small scratch ----------------
__global__ void zero_scratch_kernel()
{
    int idx = blockIdx.x*256 + threadIdx.x;
    if (idx < BH*Nn) g_patch[idx] = 0.f;
    if (idx < Bsz*KLD) g_keep[idx] = 0.f;
    if (idx < Nn) g_cnt[idx] = 0.f;
}

// ---------------- column sums per (b,h) ----------------
__global__ __launch_bounds__(256)
void colsum_kernel(const float* __restrict__ S)
{
    const int bh = blockIdx.x;
    const int i0 = blockIdx.y*129, i1 = min(i0+129, Nn);
    const float* Sb = S + (size_t)bh*SB;
    const int t = threadIdx.x;

    float4 acc = make_float4(0.f,0.f,0.f,0.f);
    float accl = 0.f;
    for (int i=i0;i<i1;i++){
        const float* row = Sb + (size_t)i*SLD;
        const float4 v = ((const float4*)row)[t];
        acc.x+=v.x; acc.y+=v.y; acc.z+=v.z; acc.w+=v.w;
        if (t==0) accl += row[1024];
    }
    float* base = &g_patch[bh*Nn];
    atomicAdd(&base[t*4+0], acc.x);
    atomicAdd(&base[t*4+1], acc.y);
    atomicAdd(&base[t*4+2], acc.z);
    atomicAdd(&base[t*4+3], acc.w);
    if (t==0) atomicAdd(&base[1024], accl);
}

// ---------------- combine patch means + exploration ----------------
__global__ __launch_bounds__(256)
void ucb_combine_kernel(const float* __restrict__ ucb_score, const int* __restrict__ counter)
{
    const int b = blockIdx.x, t = threadIdx.x;
    const float logc = logf((float)(*counter) + 1.0f);
    for (int jj=t; jj<Nn-1; jj+=256){
        const int j = jj + 1;
        float s = 0.f;
        #pragma unroll
        for (int h=0; h<Hh; h++){
            const float expl = sqrtf(logc / (ucb_score[h*Nn + j] + 1e-6f));
            s += g_patch[(b*Hh + h)*Nn + j] * (1.f/(float)Nn) + expl;
        }
        g_gucb[b*(Nn-1) + jj] = s * (1.f/(float)Hh);
    }
}

// ---------------- exact top-k (bitonic; ties -> lower index) ----------------
__global__ __launch_bounds__(512)
void topk_kernel()
{
    __shared__ float sv[1024];
    __shared__ int   si[1024];
    const int b = blockIdx.x, t = threadIdx.x;

    for (int j=t;j<1024;j+=512){ sv[j] = g_gucb[b*1024 + j]; si[j] = j; }
    __syncthreads();

    for (int k=2;k<=1024;k<<=1){
        for (int j=k>>1;j>0;j>>=1){
            for (int i=t;i<1024;i+=512){
                const int ixj = i ^ j;
                if (ixj > i){
                    float v1 = sv[i], v2 = sv[ixj];
                    int  i1 = si[i],  i2 = si[ixj];
                    const bool before = (v1 > v2) || (v1 == v2 && i1 < i2);
                    const bool dirDesc = ((i & k) == 0);
                    if (dirDesc ? (!before) : before){
                        sv[i]=v2; sv[ixj]=v1; si[i]=i2; si[ixj]=i1;
                    }
                }
            }
            __syncthreads();
        }
    }

    if (t < KSEL){
        const int tok = si[t] + 1;
        g_keep[b*KLD + tok] = 1.f;
        atomicAdd(&g_cnt[tok], 1.f);
    }
    if (t == 0) g_keep[b*KLD + 0] = 1.f;
}

// ---------------- score_delta ----------------
__global__ void score_delta_kernel(float* __restrict__ out2)
{
    int idx = blockIdx.x*256 + threadIdx.x;
    if (idx < Hh*Nn) out2[idx] = g_cnt[idx % Nn] * (1.f/(float)Bsz);
}

// =======================================================================
extern "C" void kernel_launch(void* const* d_in, const int* in_sizes, int n_in,
                              void* d_out, int out_size)
{
    const float* x       = (const float*)d_in[0];
    const float* ucbsc   = (const float*)d_in[1];
    const float* Wqkv    = (const float*)d_in[2];
    const float* Wproj   = (const float*)d_in[3];
    const float* bproj   = (const float*)d_in[4];
    const int*   counter = (const int*)d_in[5];
    const int*   enabled = (const int*)d_in[6];
    float* out = (float*)d_out;

    float *qkv, *S, *ctx;
    cudaGetSymbolAddress((void**)&qkv, g_qkv);
    cudaGetSymbolAddress((void**)&S,   g_S);
    cudaGetSymbolAddress((void**)&ctx, g_ctx);

    // 0) zero scratch (independent)
    zero_scratch_kernel<<<(BH*Nn + 255)/256, 256>>>();

    // 1) qkv = x @ W_qkv   [4100 x 2304 x 768]
    {
        dim3 grid(2304/128, (Bsz*Nn + 127)/128);
        mma_gemm_nn<false><<<grid, 256>>>(x, Wqkv, nullptr, qkv,
                                          Bsz*Nn, 3*Cc, Cc, Cc, 3*Cc, 3*Cc);
    }
    // 2) S = 0.125 * Q @ K^T  per (b,h)
    {
        dim3 grid((Nn+127)/128, (Nn+127)/128, BH);
        mma_gemm_qk<<<grid, 256>>>(qkv, S);
    }
    // 3) softmax rows
    softmax_kernel<<<BH*Nn, 256>>>(S);

    // 4) column sums, ucb combine, top-k
    { dim3 grid(BH, 8); colsum_kernel<<<grid, 256>>>(S); }
    ucb_combine_kernel<<<Bsz, 256>>>(ucbsc, counter);
    topk_kernel<<<Bsz, 512>>>();

    // 5) fused prune+renorm+context GEMM
    {
        dim3 grid(1, (Nn+127)/128, BH);
        mma_gemm_ctx<<<grid, 256>>>(S, qkv, ctx, counter, enabled);
    }
    // 6) out = ctx @ W_proj + b_proj
    {
        dim3 grid(768/128, (Bsz*Nn + 127)/128);
        mma_gemm_nn<true><<<grid, 256>>>(ctx, Wproj, bproj, out,
                                         Bsz*Nn, Cc, Cc, Cc, Cc, Cc);
    }
    // 7) score_delta
    if (out_size >= Bsz*Nn*Cc + Hh*Nn) {
        score_delta_kernel<<<(Hh*Nn + 255)/256, 256>>>(out + (size_t)Bsz*Nn*Cc);
    }
}

// round 10
// speedup vs baseline: 1.0127x; 1.0127x over previous
#include <cuda_runtime.h>
#include <math.h>
#include <stdint.h>

// ---------------- problem constants ----------------
#define Bsz 4
#define Nn  1025
#define Cc  768
#define Hh  12
#define Dh  64
#define BH  (Bsz*Hh)           // 48
#define SLD 1028               // padded row stride for S
#define KLD 1028               // padded row stride for keep mask (16B-aligned rows)
#define SB  ((size_t)Nn*SLD)
#define KSEL 256

// ---------------- scratch (device globals; allocs forbidden) ----------------
__device__ float g_qkv[(size_t)Bsz*Nn*3*Cc];
__device__ float g_S  [(size_t)BH*Nn*SLD];
__device__ float g_ctx[(size_t)Bsz*Nn*Cc];
__device__ float g_patch[BH*Nn];
__device__ float g_gucb[Bsz*(Nn-1)];
__device__ float g_keep[Bsz*KLD];
__device__ float g_cnt[Nn];

// ---------------- tf32 helpers ----------------
__device__ __forceinline__ uint32_t f2tf(float x){
    uint32_t r; asm("cvt.rna.tf32.f32 %0, %1;" : "=r"(r) : "f"(x)); return r;
}
__device__ __forceinline__ void mma8(float* d, const uint32_t* a, const uint32_t* b){
    asm volatile("mma.sync.aligned.m16n8k8.row.col.f32.tf32.tf32.f32 "
        "{%0,%1,%2,%3}, {%4,%5,%6,%7}, {%8,%9}, {%0,%1,%2,%3};"
        : "+f"(d[0]), "+f"(d[1]), "+f"(d[2]), "+f"(d[3])
        : "r"(a[0]), "r"(a[1]), "r"(a[2]), "r"(a[3]), "r"(b[0]), "r"(b[1]));
}

// =====================================================================
// mma_gemm_nn: C[M,N] = A[M,K] @ B[K,N] (+bias).  tf32 tensor cores.
// Block tile 128x128, BK=16, 8 warps (4m x 2n), warp tile 32m x 64n.
// =====================================================================
template<bool BIAS>
__global__ __launch_bounds__(256,1)
void mma_gemm_nn(const float* __restrict__ A, const float* __restrict__ B,
                 const float* __restrict__ bias, float* __restrict__ C,
                 int M, int N, int K, int lda, int ldb, int ldc)
{
    __shared__ uint32_t As[2][16][136];
    __shared__ uint32_t Bs[2][16][136];
    const int tid = threadIdx.x, lane = tid & 31, warp = tid >> 5;
    const int wm = warp & 3;
    const int wN = warp >> 2;                      // 0..1
    const int m0 = blockIdx.y*128, n0 = blockIdx.x*128;

    const int ar = tid >> 2, ak = (tid & 3) << 2;
    const bool aok0 = (m0 + ar)      < M;
    const bool aok1 = (m0 + ar + 64) < M;
    const float* Ap0 = A + (size_t)(m0+ar)*lda + ak;
    const float* Ap1 = A + (size_t)(m0+ar+64)*lda + ak;
    const int bk = tid >> 5, bn = (tid & 31) << 2;
    const float* Bp0 = B + (size_t)bk*ldb + n0 + bn;
    const float* Bp1 = B + (size_t)(bk+8)*ldb + n0 + bn;

    const float4 z4 = make_float4(0.f,0.f,0.f,0.f);
    float4 a0 = aok0 ? *(const float4*)Ap0 : z4;
    float4 a1 = aok1 ? *(const float4*)Ap1 : z4;
    float4 b0 = *(const float4*)Bp0;
    float4 b1 = *(const float4*)Bp1;

    auto stA = [&](int buf, const float4& v0, const float4& v1){
        As[buf][ak+0][ar]=f2tf(v0.x); As[buf][ak+1][ar]=f2tf(v0.y);
        As[buf][ak+2][ar]=f2tf(v0.z); As[buf][ak+3][ar]=f2tf(v0.w);
        As[buf][ak+0][ar+64]=f2tf(v1.x); As[buf][ak+1][ar+64]=f2tf(v1.y);
        As[buf][ak+2][ar+64]=f2tf(v1.z); As[buf][ak+3][ar+64]=f2tf(v1.w);
    };
    auto stB = [&](int buf, const float4& v0, const float4& v1){
        *(uint4*)&Bs[buf][bk  ][bn] = make_uint4(f2tf(v0.x),f2tf(v0.y),f2tf(v0.z),f2tf(v0.w));
        *(uint4*)&Bs[buf][bk+8][bn] = make_uint4(f2tf(v1.x),f2tf(v1.y),f2tf(v1.z),f2tf(v1.w));
    };

    stA(0,a0,a1); stB(0,b0,b1); __syncthreads();

    float acc[2][8][4];
    #pragma unroll
    for (int i=0;i<2;i++)
        #pragma unroll
        for (int j=0;j<8;j++)
            #pragma unroll
            for (int q=0;q<4;q++) acc[i][j][q]=0.f;

    const int nk = K >> 4;
    for (int t=0;t<nk;t++){
        const int cur = t & 1;
        if (t+1<nk){
            a0 = aok0 ? *(const float4*)(Ap0 + (t+1)*16) : z4;
            a1 = aok1 ? *(const float4*)(Ap1 + (t+1)*16) : z4;
            b0 = *(const float4*)(Bp0 + (size_t)(t+1)*16*ldb);
            b1 = *(const float4*)(Bp1 + (size_t)(t+1)*16*ldb);
        }
        #pragma unroll
        for (int ks=0;ks<2;ks++){
            const int kb = ks*8;
            uint32_t af[2][4], bf[8][2];
            #pragma unroll
            for (int mt=0;mt<2;mt++){
                const int r = wm*32 + mt*16 + (lane>>2);
                af[mt][0] = As[cur][kb+(lane&3)  ][r];
                af[mt][1] = As[cur][kb+(lane&3)  ][r+8];
                af[mt][2] = As[cur][kb+(lane&3)+4][r];
                af[mt][3] = As[cur][kb+(lane&3)+4][r+8];
            }
            #pragma unroll
            for (int nt=0;nt<8;nt++){
                const int c = wN*64 + nt*8 + (lane>>2);
                bf[nt][0] = Bs[cur][kb+(lane&3)  ][c];
                bf[nt][1] = Bs[cur][kb+(lane&3)+4][c];
            }
            #pragma unroll
            for (int mt=0;mt<2;mt++)
                #pragma unroll
                for (int nt=0;nt<8;nt++) mma8(acc[mt][nt], af[mt], bf[nt]);
        }
        if (t+1<nk){ const int nxt = cur^1; stA(nxt,a0,a1); stB(nxt,b0,b1); }
        __syncthreads();
    }

    #pragma unroll
    for (int mt=0;mt<2;mt++){
        const int r0 = m0 + wm*32 + mt*16 + (lane>>2);
        #pragma unroll
        for (int nt=0;nt<8;nt++){
            const int gc = n0 + wN*64 + nt*8 + (lane&3)*2;
            float bx=0.f, by=0.f;
            if (BIAS){ bx = bias[gc]; by = bias[gc+1]; }
            if (r0 < M){
                float2 v; v.x = acc[mt][nt][0]+bx; v.y = acc[mt][nt][1]+by;
                *(float2*)&C[(size_t)r0*ldc + gc] = v;
            }
            if (r0+8 < M){
                float2 v; v.x = acc[mt][nt][2]+bx; v.y = acc[mt][nt][3]+by;
                *(float2*)&C[(size_t)(r0+8)*ldc + gc] = v;
            }
        }
    }
}

// =====================================================================
// mma_gemm_qk: S[bh] = 0.125 * Q @ K^T.  Operand rows stride 3*Cc.
// =====================================================================
__global__ __launch_bounds__(256,1)
void mma_gemm_qk(const float* __restrict__ QKV, float* __restrict__ S)
{
    const int bh = blockIdx.z, b = bh / Hh, h = bh % Hh;
    const float* Q  = QKV + (size_t)b*Nn*3*Cc + (size_t)h*Dh;
    const float* Km = Q + Cc;
    float* Cs = S + (size_t)bh * SB;

    __shared__ uint32_t As[2][16][136];
    __shared__ uint32_t Bs[2][16][136];
    const int tid = threadIdx.x, lane = tid & 31, warp = tid >> 5;
    const int wm = warp & 3, wN = warp >> 2;
    const int m0 = blockIdx.y*128, n0 = blockIdx.x*128;

    const int ar = tid >> 2, ak = (tid & 3) << 2;
    const bool aok0 = (m0 + ar)      < Nn;
    const bool aok1 = (m0 + ar + 64) < Nn;
    const bool bok0 = (n0 + ar)      < Nn;
    const bool bok1 = (n0 + ar + 64) < Nn;
    const float* Ap0 = Q  + (size_t)(m0+ar)*(3*Cc) + ak;
    const float* Ap1 = Q  + (size_t)(m0+ar+64)*(3*Cc) + ak;
    const float* Bp0 = Km + (size_t)(n0+ar)*(3*Cc) + ak;
    const float* Bp1 = Km + (size_t)(n0+ar+64)*(3*Cc) + ak;

    const float4 z4 = make_float4(0.f,0.f,0.f,0.f);
    float4 a0 = aok0 ? *(const float4*)Ap0 : z4;
    float4 a1 = aok1 ? *(const float4*)Ap1 : z4;
    float4 b0 = bok0 ? *(const float4*)Bp0 : z4;
    float4 b1 = bok1 ? *(const float4*)Bp1 : z4;

    auto stT = [&](uint32_t (*dst)[136], const float4& v0, const float4& v1){
        dst[ak+0][ar]=f2tf(v0.x); dst[ak+1][ar]=f2tf(v0.y);
        dst[ak+2][ar]=f2tf(v0.z); dst[ak+3][ar]=f2tf(v0.w);
        dst[ak+0][ar+64]=f2tf(v1.x); dst[ak+1][ar+64]=f2tf(v1.y);
        dst[ak+2][ar+64]=f2tf(v1.z); dst[ak+3][ar+64]=f2tf(v1.w);
    };

    stT(As[0],a0,a1); stT(Bs[0],b0,b1); __syncthreads();

    float acc[2][8][4];
    #pragma unroll
    for (int i=0;i<2;i++)
        #pragma unroll
        for (int j=0;j<8;j++)
            #pragma unroll
            for (int q=0;q<4;q++) acc[i][j][q]=0.f;

    const int nk = Dh >> 4;   // 4
    for (int t=0;t<nk;t++){
        const int cur = t & 1;
        if (t+1<nk){
            a0 = aok0 ? *(const float4*)(Ap0 + (t+1)*16) : z4;
            a1 = aok1 ? *(const float4*)(Ap1 + (t+1)*16) : z4;
            b0 = bok0 ? *(const float4*)(Bp0 + (t+1)*16) : z4;
            b1 = bok1 ? *(const float4*)(Bp1 + (t+1)*16) : z4;
        }
        #pragma unroll
        for (int ks=0;ks<2;ks++){
            const int kb = ks*8;
            uint32_t af[2][4], bf[8][2];
            #pragma unroll
            for (int mt=0;mt<2;mt++){
                const int r = wm*32 + mt*16 + (lane>>2);
                af[mt][0] = As[cur][kb+(lane&3)  ][r];
                af[mt][1] = As[cur][kb+(lane&3)  ][r+8];
                af[mt][2] = As[cur][kb+(lane&3)+4][r];
                af[mt][3] = As[cur][kb+(lane&3)+4][r+8];
            }
            #pragma unroll
            for (int nt=0;nt<8;nt++){
                const int c = wN*64 + nt*8 + (lane>>2);
                bf[nt][0] = Bs[cur][kb+(lane&3)  ][c];
                bf[nt][1] = Bs[cur][kb+(lane&3)+4][c];
            }
            #pragma unroll
            for (int mt=0;mt<2;mt++)
                #pragma unroll
                for (int nt=0;nt<8;nt++) mma8(acc[mt][nt], af[mt], bf[nt]);
        }
        if (t+1<nk){ const int nxt = cur^1; stT(As[nxt],a0,a1); stT(Bs[nxt],b0,b1); }
        __syncthreads();
    }

    const float alpha = 0.125f;
    #pragma unroll
    for (int mt=0;mt<2;mt++){
        const int r0 = m0 + wm*32 + mt*16 + (lane>>2);
        #pragma unroll
        for (int nt=0;nt<8;nt++){
            const int gc = n0 + wN*64 + nt*8 + (lane&3)*2;
            if (r0 < Nn){
                if (gc+1 < Nn){
                    float2 v; v.x=acc[mt][nt][0]*alpha; v.y=acc[mt][nt][1]*alpha;
                    *(float2*)&Cs[(size_t)r0*SLD + gc] = v;
                } else if (gc < Nn) Cs[(size_t)r0*SLD + gc] = acc[mt][nt][0]*alpha;
            }
            if (r0+8 < Nn){
                if (gc+1 < Nn){
                    float2 v; v.x=acc[mt][nt][2]*alpha; v.y=acc[mt][nt][3]*alpha;
                    *(float2*)&Cs[(size_t)(r0+8)*SLD + gc] = v;
                } else if (gc < Nn) Cs[(size_t)(r0+8)*SLD + gc] = acc[mt][nt][2]*alpha;
            }
        }
    }
}

// =====================================================================
// mma_gemm_ctx: fused prune-mask + renorm + (pruned @ V).
// =====================================================================
__global__ __launch_bounds__(256,1)
void mma_gemm_ctx(const float* __restrict__ S, const float* __restrict__ QKV,
                  float* __restrict__ ctx, const int* __restrict__ counter,
                  const int* __restrict__ enabled)
{
    const int bh = blockIdx.z, b = bh / Hh, h = bh % Hh;
    const bool prune = ((*enabled) != 0) && ((*counter) > 50);
    const float* Sp = S + (size_t)bh*SB;
    const float* V  = QKV + (size_t)b*Nn*3*Cc + 2*(size_t)Cc + (size_t)h*Dh;
    const float* kp = g_keep + (size_t)b*KLD;   // 16B-aligned rows
    float* Cp = ctx + (size_t)b*Nn*Cc + (size_t)h*Dh;

    __shared__ uint32_t As[2][16][136];
    __shared__ uint32_t Bs[2][16][72];
    __shared__ float zsh[128];

    const int tid = threadIdx.x, lane = tid & 31, warp = tid >> 5;
    const int wm = warp & 3, wN = warp >> 2;
    const int m0 = blockIdx.y*128;

    const int ar = tid >> 2, ak = (tid & 3) << 2;
    const int gm0 = m0 + ar, gm1 = m0 + ar + 64;
    const bool aok0 = gm0 < Nn, aok1 = gm1 < Nn;
    const float keep0 = (prune && aok0) ? kp[gm0] : 1.f;
    const float keep1 = (prune && aok1) ? kp[gm1] : 1.f;
    const float* Ap0 = Sp + (size_t)(aok0 ? gm0 : 0)*SLD;
    const float* Ap1 = Sp + (size_t)(aok1 ? gm1 : 0)*SLD;
    const int bk = tid >> 4, bn = (tid & 15) << 2;
    const float* Bp = V + (size_t)bk*(3*Cc) + bn;

    const float4 z4 = make_float4(0.f,0.f,0.f,0.f);
    float z0 = 0.f, z1 = 0.f;

    auto ldrow = [&](const float* rowp, float keepi, int k0, bool ok, float& zacc)->float4{
        float4 v = z4;
        if (ok){
            const int c = k0 + ak;
            if (c + 3 < Nn) v = *(const float4*)(rowp + c);
            else {
                if (c   < Nn) v.x = rowp[c];
                if (c+1 < Nn) v.y = rowp[c+1];
                if (c+2 < Nn) v.z = rowp[c+2];
                if (c+3 < Nn) v.w = rowp[c+3];
            }
            if (keepi < 0.5f){
                float4 kv = z4;
                if (c + 3 < Nn) kv = *(const float4*)(kp + c);   // kp rows 16B-aligned now
                else {
                    if (c   < Nn) kv.x = kp[c];
                    if (c+1 < Nn) kv.y = kp[c+1];
                    if (c+2 < Nn) kv.z = kp[c+2];
                    if (c+3 < Nn) kv.w = kp[c+3];
                }
                v.x*=kv.x; v.y*=kv.y; v.z*=kv.z; v.w*=kv.w;
            }
            zacc += (v.x+v.y)+(v.z+v.w);
        }
        return v;
    };
    auto ldB = [&](int k0)->float4{
        return (k0 + bk < Nn) ? *(const float4*)(Bp + (size_t)k0*(3*Cc)) : z4;
    };
    auto stA = [&](int buf, const float4& v0, const float4& v1){
        As[buf][ak+0][ar]=f2tf(v0.x); As[buf][ak+1][ar]=f2tf(v0.y);
        As[buf][ak+2][ar]=f2tf(v0.z); As[buf][ak+3][ar]=f2tf(v0.w);
        As[buf][ak+0][ar+64]=f2tf(v1.x); As[buf][ak+1][ar+64]=f2tf(v1.y);
        As[buf][ak+2][ar+64]=f2tf(v1.z); As[buf][ak+3][ar+64]=f2tf(v1.w);
    };
    auto stB = [&](int buf, const float4& v){
        *(uint4*)&Bs[buf][bk][bn] = make_uint4(f2tf(v.x),f2tf(v.y),f2tf(v.z),f2tf(v.w));
    };

    float4 a0 = ldrow(Ap0, keep0, 0, aok0, z0);
    float4 a1 = ldrow(Ap1, keep1, 0, aok1, z1);
    float4 bv = ldB(0);
    stA(0,a0,a1); stB(0,bv); __syncthreads();

    float acc[2][4][4];
    #pragma unroll
    for (int i=0;i<2;i++)
        #pragma unroll
        for (int j=0;j<4;j++)
            #pragma unroll
            for (int q=0;q<4;q++) acc[i][j][q]=0.f;

    const int nk = (Nn + 15) >> 4;   // 65
    for (int t=0;t<nk;t++){
        const int cur = t & 1;
        if (t+1<nk){
            a0 = ldrow(Ap0, keep0, (t+1)*16, aok0, z0);
            a1 = ldrow(Ap1, keep1, (t+1)*16, aok1, z1);
            bv = ldB((t+1)*16);
        }
        #pragma unroll
        for (int ks=0;ks<2;ks++){
            const int kb = ks*8;
            uint32_t af[2][4], bf[4][2];
            #pragma unroll
            for (int mt=0;mt<2;mt++){
                const int r = wm*32 + mt*16 + (lane>>2);
                af[mt][0] = As[cur][kb+(lane&3)  ][r];
                af[mt][1] = As[cur][kb+(lane&3)  ][r+8];
                af[mt][2] = As[cur][kb+(lane&3)+4][r];
                af[mt][3] = As[cur][kb+(lane&3)+4][r+8];
            }
            #pragma unroll
            for (int nt=0;nt<4;nt++){
                const int c = wN*32 + nt*8 + (lane>>2);
                bf[nt][0] = Bs[cur][kb+(lane&3)  ][c];
                bf[nt][1] = Bs[cur][kb+(lane&3)+4][c];
            }
            #pragma unroll
            for (int mt=0;mt<2;mt++)
                #pragma unroll
                for (int nt=0;nt<4;nt++) mma8(acc[mt][nt], af[mt], bf[nt]);
        }
        if (t+1<nk){ const int nxt = cur^1; stA(nxt,a0,a1); stB(nxt,bv); }
        __syncthreads();
    }

    z0 += __shfl_xor_sync(0xffffffffu, z0, 1);
    z0 += __shfl_xor_sync(0xffffffffu, z0, 2);
    z1 += __shfl_xor_sync(0xffffffffu, z1, 1);
    z1 += __shfl_xor_sync(0xffffffffu, z1, 2);
    if ((lane & 3) == 0){ zsh[ar] = z0; zsh[ar+64] = z1; }
    __syncthreads();

    #pragma unroll
    for (int mt=0;mt<2;mt++){
        const int lr = wm*32 + mt*16 + (lane>>2);
        const int r0 = m0 + lr;
        const float iz0 = prune ? 1.f/(zsh[lr]   + 1e-8f) : 1.f;
        const float iz1 = prune ? 1.f/(zsh[lr+8] + 1e-8f) : 1.f;
        #pragma unroll
        for (int nt=0;nt<4;nt++){
            const int gc = wN*32 + nt*8 + (lane&3)*2;
            if (r0 < Nn){
                float2 v; v.x=acc[mt][nt][0]*iz0; v.y=acc[mt][nt][1]*iz0;
                *(float2*)&Cp[(size_t)r0*Cc + gc] = v;
            }
            if (r0+8 < Nn){
                float2 v; v.x=acc[mt][nt][2]*iz1; v.y=acc[mt][nt][3]*iz1;
                *(float2*)&Cp[(size_t)(r0+8)*Cc + gc] = v;
            }
        }
    }
}

// ---------------- row softmax (vectorized) ----------------
__global__ __launch_bounds__(256)
void softmax_kernel(float* __restrict__ S)
{
    const int r = blockIdx.x;
    float* row = S + (size_t)(r / Nn)*SB + (size_t)(r % Nn)*SLD;
    const int t = threadIdx.x;
    __shared__ float red[256];

    float4 v = ((const float4*)row)[t];
    const float last = row[1024];
    float mx = fmaxf(fmaxf(v.x,v.y), fmaxf(v.z,v.w));
    mx = fmaxf(mx, last);
    red[t] = mx; __syncthreads();
    for (int s=128;s>0;s>>=1){ if (t<s) red[t]=fmaxf(red[t],red[t+s]); __syncthreads(); }
    mx = red[0]; __syncthreads();

    float4 e;
    e.x = __expf(v.x-mx); e.y = __expf(v.y-mx);
    e.z = __expf(v.z-mx); e.w = __expf(v.w-mx);
    const float el = __expf(last-mx);
    float sm = (e.x+e.y)+(e.z+e.w);
    if (t==0) sm += el;
    red[t] = sm; __syncthreads();
    for (int s=128;s>0;s>>=1){ if (t<s) red[t]+=red[t+s]; __syncthreads(); }
    const float inv = 1.f/red[0];
    e.x*=inv; e.y*=inv; e.z*=inv; e.w*=inv;
    ((float4*)row)[t] = e;
    if (t==0) row[1024] = el*inv;
}

// ---------------- zero small scratch ----------------
__global__ void zero_scratch_kernel()
{
    int idx = blockIdx.x*256 + threadIdx.x;
    if (idx < BH*Nn) g_patch[idx] = 0.f;
    if (idx < Bsz*KLD) g_keep[idx] = 0.f;
    if (idx < Nn) g_cnt[idx] = 0.f;
}

// ---------------- column sums per (b,h) ----------------
__global__ __launch_bounds__(256)
void colsum_kernel(const float* __restrict__ S)
{
    const int bh = blockIdx.x;
    const int i0 = blockIdx.y*129, i1 = min(i0+129, Nn);
    const float* Sb = S + (size_t)bh*SB;
    const int t = threadIdx.x;

    float4 acc = make_float4(0.f,0.f,0.f,0.f);
    float accl = 0.f;
    for (int i=i0;i<i1;i++){
        const float* row = Sb + (size_t)i*SLD;
        const float4 v = ((const float4*)row)[t];
        acc.x+=v.x; acc.y+=v.y; acc.z+=v.z; acc.w+=v.w;
        if (t==0) accl += row[1024];
    }
    float* base = &g_patch[bh*Nn];
    atomicAdd(&base[t*4+0], acc.x);
    atomicAdd(&base[t*4+1], acc.y);
    atomicAdd(&base[t*4+2], acc.z);
    atomicAdd(&base[t*4+3], acc.w);
    if (t==0) atomicAdd(&base[1024], accl);
}

// ---------------- combine patch means + exploration ----------------
__global__ __launch_bounds__(256)
void ucb_combine_kernel(const float* __restrict__ ucb_score, const int* __restrict__ counter)
{
    const int b = blockIdx.x, t = threadIdx.x;
    const float logc = logf((float)(*counter) + 1.0f);
    for (int jj=t; jj<Nn-1; jj+=256){
        const int j = jj + 1;
        float s = 0.f;
        #pragma unroll
        for (int h=0; h<Hh; h++){
            const float expl = sqrtf(logc / (ucb_score[h*Nn + j] + 1e-6f));
            s += g_patch[(b*Hh + h)*Nn + j] * (1.f/(float)Nn) + expl;
        }
        g_gucb[b*(Nn-1) + jj] = s * (1.f/(float)Hh);
    }
}

// ---------------- exact top-k (bitonic; ties -> lower index) ----------------
__global__ __launch_bounds__(512)
void topk_kernel()
{
    __shared__ float sv[1024];
    __shared__ int   si[1024];
    const int b = blockIdx.x, t = threadIdx.x;

    for (int j=t;j<1024;j+=512){ sv[j] = g_gucb[b*1024 + j]; si[j] = j; }
    __syncthreads();

    for (int k=2;k<=1024;k<<=1){
        for (int j=k>>1;j>0;j>>=1){
            for (int i=t;i<1024;i+=512){
                const int ixj = i ^ j;
                if (ixj > i){
                    float v1 = sv[i], v2 = sv[ixj];
                    int  i1 = si[i],  i2 = si[ixj];
                    const bool before = (v1 > v2) || (v1 == v2 && i1 < i2);
                    const bool dirDesc = ((i & k) == 0);
                    if (dirDesc ? (!before) : before){
                        sv[i]=v2; sv[ixj]=v1; si[i]=i2; si[ixj]=i1;
                    }
                }
            }
            __syncthreads();
        }
    }

    if (t < KSEL){
        const int tok = si[t] + 1;
        g_keep[b*KLD + tok] = 1.f;
        atomicAdd(&g_cnt[tok], 1.f);
    }
    if (t == 0) g_keep[b*KLD + 0] = 1.f;
}

// ---------------- score_delta ----------------
__global__ void score_delta_kernel(float* __restrict__ out2)
{
    int idx = blockIdx.x*256 + threadIdx.x;
    if (idx < Hh*Nn) out2[idx] = g_cnt[idx % Nn] * (1.f/(float)Bsz);
}

// =======================================================================
extern "C" void kernel_launch(void* const* d_in, const int* in_sizes, int n_in,
                              void* d_out, int out_size)
{
    const float* x       = (const float*)d_in[0];
    const float* ucbsc   = (const float*)d_in[1];
    const float* Wqkv    = (const float*)d_in[2];
    const float* Wproj   = (const float*)d_in[3];
    const float* bproj   = (const float*)d_in[4];
    const int*   counter = (const int*)d_in[5];
    const int*   enabled = (const int*)d_in[6];
    float* out = (float*)d_out;

    float *qkv, *S, *ctx;
    cudaGetSymbolAddress((void**)&qkv, g_qkv);
    cudaGetSymbolAddress((void**)&S,   g_S);
    cudaGetSymbolAddress((void**)&ctx, g_ctx);

    // 0) zero scratch (independent)
    zero_scratch_kernel<<<(BH*Nn + 255)/256, 256>>>();

    // 1) qkv = x @ W_qkv   [4100 x 2304 x 768]
    {
        dim3 grid(2304/128, (Bsz*Nn + 127)/128);
        mma_gemm_nn<false><<<grid, 256>>>(x, Wqkv, nullptr, qkv,
                                          Bsz*Nn, 3*Cc, Cc, Cc, 3*Cc, 3*Cc);
    }
    // 2) S = 0.125 * Q @ K^T  per (b,h)
    {
        dim3 grid((Nn+127)/128, (Nn+127)/128, BH);
        mma_gemm_qk<<<grid, 256>>>(qkv, S);
    }
    // 3) softmax rows
    softmax_kernel<<<BH*Nn, 256>>>(S);

    // 4) column sums, ucb combine, top-k
    { dim3 grid(BH, 8); colsum_kernel<<<grid, 256>>>(S); }
    ucb_combine_kernel<<<Bsz, 256>>>(ucbsc, counter);
    topk_kernel<<<Bsz, 512>>>();

    // 5) fused prune+renorm+context GEMM
    {
        dim3 grid(1, (Nn+127)/128, BH);
        mma_gemm_ctx<<<grid, 256>>>(S, qkv, ctx, counter, enabled);
    }
    // 6) out = ctx @ W_proj + b_proj
    {
        dim3 grid(768/128, (Bsz*Nn + 127)/128);
        mma_gemm_nn<true><<<grid, 256>>>(ctx, Wproj, bproj, out,
                                         Bsz*Nn, Cc, Cc, Cc, Cc, Cc);
    }
    // 7) score_delta
    if (out_size >= Bsz*Nn*Cc + Hh*Nn) {
        score_delta_kernel<<<(Hh*Nn + 255)/256, 256>>>(out + (size_t)Bsz*Nn*Cc);
    }
}

// round 12
// speedup vs baseline: 1.0133x; 1.0006x over previous
#include <cuda_runtime.h>
#include <math.h>
#include <stdint.h>

// ---------------- problem constants ----------------
#define Bsz 4
#define Nn  1025
#define Cc  768
#define Hh  12
#define Dh  64
#define BH  (Bsz*Hh)           // 48
#define SLD 1028               // padded row stride for S
#define KLD 1028               // padded row stride for keep mask (16B-aligned rows)
#define SB  ((size_t)Nn*SLD)
#define KSEL 256

// ---------------- scratch (device globals; allocs forbidden) ----------------
__device__ float g_qkv[(size_t)Bsz*Nn*3*Cc];
__device__ float g_S  [(size_t)BH*Nn*SLD];
__device__ float g_ctx[(size_t)Bsz*Nn*Cc];
__device__ float g_patch[BH*Nn];
__device__ float g_gucb[Bsz*(Nn-1)];
__device__ float g_keep[Bsz*KLD];
__device__ float g_cnt[Nn];

// ---------------- tf32 helpers ----------------
__device__ __forceinline__ uint32_t f2tf(float x){
    uint32_t r; asm("cvt.rna.tf32.f32 %0, %1;" : "=r"(r) : "f"(x)); return r;
}
__device__ __forceinline__ void mma8(float* d, const uint32_t* a, const uint32_t* b){
    asm volatile("mma.sync.aligned.m16n8k8.row.col.f32.tf32.tf32.f32 "
        "{%0,%1,%2,%3}, {%4,%5,%6,%7}, {%8,%9}, {%0,%1,%2,%3};"
        : "+f"(d[0]), "+f"(d[1]), "+f"(d[2]), "+f"(d[3])
        : "r"(a[0]), "r"(a[1]), "r"(a[2]), "r"(a[3]), "r"(b[0]), "r"(b[1]));
}

// =====================================================================
// mma_gemm_nn: C[M,N] = A[M,K] @ B[K,N] (+bias).  tf32 tensor cores.
// Block tile 128x128, BK=16, 8 warps (4m x 2n), warp tile 32m x 64n.
// =====================================================================
template<bool BIAS>
__global__ __launch_bounds__(256,1)
void mma_gemm_nn(const float* __restrict__ A, const float* __restrict__ B,
                 const float* __restrict__ bias, float* __restrict__ C,
                 int M, int N, int K, int lda, int ldb, int ldc)
{
    __shared__ uint32_t As[2][16][136];
    __shared__ uint32_t Bs[2][16][136];
    const int tid = threadIdx.x, lane = tid & 31, warp = tid >> 5;
    const int wm = warp & 3;
    const int wN = warp >> 2;                      // 0..1
    const int m0 = blockIdx.y*128, n0 = blockIdx.x*128;

    const int ar = tid >> 2, ak = (tid & 3) << 2;
    const bool aok0 = (m0 + ar)      < M;
    const bool aok1 = (m0 + ar + 64) < M;
    const float* Ap0 = A + (size_t)(m0+ar)*lda + ak;
    const float* Ap1 = A + (size_t)(m0+ar+64)*lda + ak;
    const int bk = tid >> 5, bn = (tid & 31) << 2;
    const float* Bp0 = B + (size_t)bk*ldb + n0 + bn;
    const float* Bp1 = B + (size_t)(bk+8)*ldb + n0 + bn;

    const float4 z4 = make_float4(0.f,0.f,0.f,0.f);
    float4 a0 = aok0 ? *(const float4*)Ap0 : z4;
    float4 a1 = aok1 ? *(const float4*)Ap1 : z4;
    float4 b0 = *(const float4*)Bp0;
    float4 b1 = *(const float4*)Bp1;

    auto stA = [&](int buf, const float4& v0, const float4& v1){
        As[buf][ak+0][ar]=f2tf(v0.x); As[buf][ak+1][ar]=f2tf(v0.y);
        As[buf][ak+2][ar]=f2tf(v0.z); As[buf][ak+3][ar]=f2tf(v0.w);
        As[buf][ak+0][ar+64]=f2tf(v1.x); As[buf][ak+1][ar+64]=f2tf(v1.y);
        As[buf][ak+2][ar+64]=f2tf(v1.z); As[buf][ak+3][ar+64]=f2tf(v1.w);
    };
    auto stB = [&](int buf, const float4& v0, const float4& v1){
        *(uint4*)&Bs[buf][bk  ][bn] = make_uint4(f2tf(v0.x),f2tf(v0.y),f2tf(v0.z),f2tf(v0.w));
        *(uint4*)&Bs[buf][bk+8][bn] = make_uint4(f2tf(v1.x),f2tf(v1.y),f2tf(v1.z),f2tf(v1.w));
    };

    stA(0,a0,a1); stB(0,b0,b1); __syncthreads();

    float acc[2][8][4];
    #pragma unroll
    for (int i=0;i<2;i++)
        #pragma unroll
        for (int j=0;j<8;j++)
            #pragma unroll
            for (int q=0;q<4;q++) acc[i][j][q]=0.f;

    const int nk = K >> 4;
    for (int t=0;t<nk;t++){
        const int cur = t & 1;
        if (t+1<nk){
            a0 = aok0 ? *(const float4*)(Ap0 + (t+1)*16) : z4;
            a1 = aok1 ? *(const float4*)(Ap1 + (t+1)*16) : z4;
            b0 = *(const float4*)(Bp0 + (size_t)(t+1)*16*ldb);
            b1 = *(const float4*)(Bp1 + (size_t)(t+1)*16*ldb);
        }
        #pragma unroll
        for (int ks=0;ks<2;ks++){
            const int kb = ks*8;
            uint32_t af[2][4], bf[8][2];
            #pragma unroll
            for (int mt=0;mt<2;mt++){
                const int r = wm*32 + mt*16 + (lane>>2);
                af[mt][0] = As[cur][kb+(lane&3)  ][r];
                af[mt][1] = As[cur][kb+(lane&3)  ][r+8];
                af[mt][2] = As[cur][kb+(lane&3)+4][r];
                af[mt][3] = As[cur][kb+(lane&3)+4][r+8];
            }
            #pragma unroll
            for (int nt=0;nt<8;nt++){
                const int c = wN*64 + nt*8 + (lane>>2);
                bf[nt][0] = Bs[cur][kb+(lane&3)  ][c];
                bf[nt][1] = Bs[cur][kb+(lane&3)+4][c];
            }
            #pragma unroll
            for (int mt=0;mt<2;mt++)
                #pragma unroll
                for (int nt=0;nt<8;nt++) mma8(acc[mt][nt], af[mt], bf[nt]);
        }
        if (t+1<nk){ const int nxt = cur^1; stA(nxt,a0,a1); stB(nxt,b0,b1); }
        __syncthreads();
    }

    #pragma unroll
    for (int mt=0;mt<2;mt++){
        const int r0 = m0 + wm*32 + mt*16 + (lane>>2);
        #pragma unroll
        for (int nt=0;nt<8;nt++){
            const int gc = n0 + wN*64 + nt*8 + (lane&3)*2;
            float bx=0.f, by=0.f;
            if (BIAS){ bx = bias[gc]; by = bias[gc+1]; }
            if (r0 < M){
                float2 v; v.x = acc[mt][nt][0]+bx; v.y = acc[mt][nt][1]+by;
                *(float2*)&C[(size_t)r0*ldc + gc] = v;
            }
            if (r0+8 < M){
                float2 v; v.x = acc[mt][nt][2]+bx; v.y = acc[mt][nt][3]+by;
                *(float2*)&C[(size_t)(r0+8)*ldc + gc] = v;
            }
        }
    }
}

// =====================================================================
// mma_gemm_qk: S[bh] = 0.125 * Q @ K^T.  Operand rows stride 3*Cc.
// =====================================================================
__global__ __launch_bounds__(256,1)
void mma_gemm_qk(const float* __restrict__ QKV, float* __restrict__ S)
{
    const int bh = blockIdx.z, b = bh / Hh, h = bh % Hh;
    const float* Q  = QKV + (size_t)b*Nn*3*Cc + (size_t)h*Dh;
    const float* Km = Q + Cc;
    float* Cs = S + (size_t)bh * SB;

    __shared__ uint32_t As[2][16][136];
    __shared__ uint32_t Bs[2][16][136];
    const int tid = threadIdx.x, lane = tid & 31, warp = tid >> 5;
    const int wm = warp & 3, wN = warp >> 2;
    const int m0 = blockIdx.y*128, n0 = blockIdx.x*128;

    const int ar = tid >> 2, ak = (tid & 3) << 2;
    const bool aok0 = (m0 + ar)      < Nn;
    const bool aok1 = (m0 + ar + 64) < Nn;
    const bool bok0 = (n0 + ar)      < Nn;
    const bool bok1 = (n0 + ar + 64) < Nn;
    const float* Ap0 = Q  + (size_t)(m0+ar)*(3*Cc) + ak;
    const float* Ap1 = Q  + (size_t)(m0+ar+64)*(3*Cc) + ak;
    const float* Bp0 = Km + (size_t)(n0+ar)*(3*Cc) + ak;
    const float* Bp1 = Km + (size_t)(n0+ar+64)*(3*Cc) + ak;

    const float4 z4 = make_float4(0.f,0.f,0.f,0.f);
    float4 a0 = aok0 ? *(const float4*)Ap0 : z4;
    float4 a1 = aok1 ? *(const float4*)Ap1 : z4;
    float4 b0 = bok0 ? *(const float4*)Bp0 : z4;
    float4 b1 = bok1 ? *(const float4*)Bp1 : z4;

    auto stT = [&](uint32_t (*dst)[136], const float4& v0, const float4& v1){
        dst[ak+0][ar]=f2tf(v0.x); dst[ak+1][ar]=f2tf(v0.y);
        dst[ak+2][ar]=f2tf(v0.z); dst[ak+3][ar]=f2tf(v0.w);
        dst[ak+0][ar+64]=f2tf(v1.x); dst[ak+1][ar+64]=f2tf(v1.y);
        dst[ak+2][ar+64]=f2tf(v1.z); dst[ak+3][ar+64]=f2tf(v1.w);
    };

    stT(As[0],a0,a1); stT(Bs[0],b0,b1); __syncthreads();

    float acc[2][8][4];
    #pragma unroll
    for (int i=0;i<2;i++)
        #pragma unroll
        for (int j=0;j<8;j++)
            #pragma unroll
            for (int q=0;q<4;q++) acc[i][j][q]=0.f;

    const int nk = Dh >> 4;   // 4
    for (int t=0;t<nk;t++){
        const int cur = t & 1;
        if (t+1<nk){
            a0 = aok0 ? *(const float4*)(Ap0 + (t+1)*16) : z4;
            a1 = aok1 ? *(const float4*)(Ap1 + (t+1)*16) : z4;
            b0 = bok0 ? *(const float4*)(Bp0 + (t+1)*16) : z4;
            b1 = bok1 ? *(const float4*)(Bp1 + (t+1)*16) : z4;
        }
        #pragma unroll
        for (int ks=0;ks<2;ks++){
            const int kb = ks*8;
            uint32_t af[2][4], bf[8][2];
            #pragma unroll
            for (int mt=0;mt<2;mt++){
                const int r = wm*32 + mt*16 + (lane>>2);
                af[mt][0] = As[cur][kb+(lane&3)  ][r];
                af[mt][1] = As[cur][kb+(lane&3)  ][r+8];
                af[mt][2] = As[cur][kb+(lane&3)+4][r];
                af[mt][3] = As[cur][kb+(lane&3)+4][r+8];
            }
            #pragma unroll
            for (int nt=0;nt<8;nt++){
                const int c = wN*64 + nt*8 + (lane>>2);
                bf[nt][0] = Bs[cur][kb+(lane&3)  ][c];
                bf[nt][1] = Bs[cur][kb+(lane&3)+4][c];
            }
            #pragma unroll
            for (int mt=0;mt<2;mt++)
                #pragma unroll
                for (int nt=0;nt<8;nt++) mma8(acc[mt][nt], af[mt], bf[nt]);
        }
        if (t+1<nk){ const int nxt = cur^1; stT(As[nxt],a0,a1); stT(Bs[nxt],b0,b1); }
        __syncthreads();
    }

    const float alpha = 0.125f;
    #pragma unroll
    for (int mt=0;mt<2;mt++){
        const int r0 = m0 + wm*32 + mt*16 + (lane>>2);
        #pragma unroll
        for (int nt=0;nt<8;nt++){
            const int gc = n0 + wN*64 + nt*8 + (lane&3)*2;
            if (r0 < Nn){
                if (gc+1 < Nn){
                    float2 v; v.x=acc[mt][nt][0]*alpha; v.y=acc[mt][nt][1]*alpha;
                    *(float2*)&Cs[(size_t)r0*SLD + gc] = v;
                } else if (gc < Nn) Cs[(size_t)r0*SLD + gc] = acc[mt][nt][0]*alpha;
            }
            if (r0+8 < Nn){
                if (gc+1 < Nn){
                    float2 v; v.x=acc[mt][nt][2]*alpha; v.y=acc[mt][nt][3]*alpha;
                    *(float2*)&Cs[(size_t)(r0+8)*SLD + gc] = v;
                } else if (gc < Nn) Cs[(size_t)(r0+8)*SLD + gc] = acc[mt][nt][2]*alpha;
            }
        }
    }
}

// =====================================================================
// mma_gemm_ctx: fused prune-mask + renorm + (pruned @ V).
// =====================================================================
__global__ __launch_bounds__(256,1)
void mma_gemm_ctx(const float* __restrict__ S, const float* __restrict__ QKV,
                  float* __restrict__ ctx, const int* __restrict__ counter,
                  const int* __restrict__ enabled)
{
    const int bh = blockIdx.z, b = bh / Hh, h = bh % Hh;
    const bool prune = ((*enabled) != 0) && ((*counter) > 50);
    const float* Sp = S + (size_t)bh*SB;
    const float* V  = QKV + (size_t)b*Nn*3*Cc + 2*(size_t)Cc + (size_t)h*Dh;
    const float* kp = g_keep + (size_t)b*KLD;   // 16B-aligned rows
    float* Cp = ctx + (size_t)b*Nn*Cc + (size_t)h*Dh;

    __shared__ uint32_t As[2][16][136];
    __shared__ uint32_t Bs[2][16][72];
    __shared__ float zsh[128];

    const int tid = threadIdx.x, lane = tid & 31, warp = tid >> 5;
    const int wm = warp & 3, wN = warp >> 2;
    const int m0 = blockIdx.y*128;

    const int ar = tid >> 2, ak = (tid & 3) << 2;
    const int gm0 = m0 + ar, gm1 = m0 + ar + 64;
    const bool aok0 = gm0 < Nn, aok1 = gm1 < Nn;
    const float keep0 = (prune && aok0) ? kp[gm0] : 1.f;
    const float keep1 = (prune && aok1) ? kp[gm1] : 1.f;
    const float* Ap0 = Sp + (size_t)(aok0 ? gm0 : 0)*SLD;
    const float* Ap1 = Sp + (size_t)(aok1 ? gm1 : 0)*SLD;
    const int bk = tid >> 4, bn = (tid & 15) << 2;
    const float* Bp = V + (size_t)bk*(3*Cc) + bn;

    const float4 z4 = make_float4(0.f,0.f,0.f,0.f);
    float z0 = 0.f, z1 = 0.f;

    auto ldrow = [&](const float* rowp, float keepi, int k0, bool ok, float& zacc)->float4{
        float4 v = z4;
        if (ok){
            const int c = k0 + ak;
            if (c + 3 < Nn) v = *(const float4*)(rowp + c);
            else {
                if (c   < Nn) v.x = rowp[c];
                if (c+1 < Nn) v.y = rowp[c+1];
                if (c+2 < Nn) v.z = rowp[c+2];
                if (c+3 < Nn) v.w = rowp[c+3];
            }
            if (keepi < 0.5f){
                float4 kv = z4;
                if (c + 3 < Nn) kv = *(const float4*)(kp + c);   // kp rows 16B-aligned now
                else {
                    if (c   < Nn) kv.x = kp[c];
                    if (c+1 < Nn) kv.y = kp[c+1];
                    if (c+2 < Nn) kv.z = kp[c+2];
                    if (c+3 < Nn) kv.w = kp[c+3];
                }
                v.x*=kv.x; v.y*=kv.y; v.z*=kv.z; v.w*=kv.w;
            }
            zacc += (v.x+v.y)+(v.z+v.w);
        }
        return v;
    };
    auto ldB = [&](int k0)->float4{
        return (k0 + bk < Nn) ? *(const float4*)(Bp + (size_t)k0*(3*Cc)) : z4;
    };
    auto stA = [&](int buf, const float4& v0, const float4& v1){
        As[buf][ak+0][ar]=f2tf(v0.x); As[buf][ak+1][ar]=f2tf(v0.y);
        As[buf][ak+2][ar]=f2tf(v0.z); As[buf][ak+3][ar]=f2tf(v0.w);
        As[buf][ak+0][ar+64]=f2tf(v1.x); As[buf][ak+1][ar+64]=f2tf(v1.y);
        As[buf][ak+2][ar+64]=f2tf(v1.z); As[buf][ak+3][ar+64]=f2tf(v1.w);
    };
    auto stB = [&](int buf, const float4& v){
        *(uint4*)&Bs[buf][bk][bn] = make_uint4(f2tf(v.x),f2tf(v.y),f2tf(v.z),f2tf(v.w));
    };

    float4 a0 = ldrow(Ap0, keep0, 0, aok0, z0);
    float4 a1 = ldrow(Ap1, keep1, 0, aok1, z1);
    float4 bv = ldB(0);
    stA(0,a0,a1); stB(0,bv); __syncthreads();

    float acc[2][4][4];
    #pragma unroll
    for (int i=0;i<2;i++)
        #pragma unroll
        for (int j=0;j<4;j++)
            #pragma unroll
            for (int q=0;q<4;q++) acc[i][j][q]=0.f;

    const int nk = (Nn + 15) >> 4;   // 65
    for (int t=0;t<nk;t++){
        const int cur = t & 1;
        if (t+1<nk){
            a0 = ldrow(Ap0, keep0, (t+1)*16, aok0, z0);
            a1 = ldrow(Ap1, keep1, (t+1)*16, aok1, z1);
            bv = ldB((t+1)*16);
        }
        #pragma unroll
        for (int ks=0;ks<2;ks++){
            const int kb = ks*8;
            uint32_t af[2][4], bf[4][2];
            #pragma unroll
            for (int mt=0;mt<2;mt++){
                const int r = wm*32 + mt*16 + (lane>>2);
                af[mt][0] = As[cur][kb+(lane&3)  ][r];
                af[mt][1] = As[cur][kb+(lane&3)  ][r+8];
                af[mt][2] = As[cur][kb+(lane&3)+4][r];
                af[mt][3] = As[cur][kb+(lane&3)+4][r+8];
            }
            #pragma unroll
            for (int nt=0;nt<4;nt++){
                const int c = wN*32 + nt*8 + (lane>>2);
                bf[nt][0] = Bs[cur][kb+(lane&3)  ][c];
                bf[nt][1] = Bs[cur][kb+(lane&3)+4][c];
            }
            #pragma unroll
            for (int mt=0;mt<2;mt++)
                #pragma unroll
                for (int nt=0;nt<4;nt++) mma8(acc[mt][nt], af[mt], bf[nt]);
        }
        if (t+1<nk){ const int nxt = cur^1; stA(nxt,a0,a1); stB(nxt,bv); }
        __syncthreads();
    }

    z0 += __shfl_xor_sync(0xffffffffu, z0, 1);
    z0 += __shfl_xor_sync(0xffffffffu, z0, 2);
    z1 += __shfl_xor_sync(0xffffffffu, z1, 1);
    z1 += __shfl_xor_sync(0xffffffffu, z1, 2);
    if ((lane & 3) == 0){ zsh[ar] = z0; zsh[ar+64] = z1; }
    __syncthreads();

    #pragma unroll
    for (int mt=0;mt<2;mt++){
        const int lr = wm*32 + mt*16 + (lane>>2);
        const int r0 = m0 + lr;
        const float iz0 = prune ? 1.f/(zsh[lr]   + 1e-8f) : 1.f;
        const float iz1 = prune ? 1.f/(zsh[lr+8] + 1e-8f) : 1.f;
        #pragma unroll
        for (int nt=0;nt<4;nt++){
            const int gc = wN*32 + nt*8 + (lane&3)*2;
            if (r0 < Nn){
                float2 v; v.x=acc[mt][nt][0]*iz0; v.y=acc[mt][nt][1]*iz0;
                *(float2*)&Cp[(size_t)r0*Cc + gc] = v;
            }
            if (r0+8 < Nn){
                float2 v; v.x=acc[mt][nt][2]*iz1; v.y=acc[mt][nt][3]*iz1;
                *(float2*)&Cp[(size_t)(r0+8)*Cc + gc] = v;
            }
        }
    }
}

// ---------------- row softmax (vectorized) ----------------
__global__ __launch_bounds__(256)
void softmax_kernel(float* __restrict__ S)
{
    const int r = blockIdx.x;
    float* row = S + (size_t)(r / Nn)*SB + (size_t)(r % Nn)*SLD;
    const int t = threadIdx.x;
    __shared__ float red[256];

    float4 v = ((const float4*)row)[t];
    const float last = row[1024];
    float mx = fmaxf(fmaxf(v.x,v.y), fmaxf(v.z,v.w));
    mx = fmaxf(mx, last);
    red[t] = mx; __syncthreads();
    for (int s=128;s>0;s>>=1){ if (t<s) red[t]=fmaxf(red[t],red[t+s]); __syncthreads(); }
    mx = red[0]; __syncthreads();

    float4 e;
    e.x = __expf(v.x-mx); e.y = __expf(v.y-mx);
    e.z = __expf(v.z-mx); e.w = __expf(v.w-mx);
    const float el = __expf(last-mx);
    float sm = (e.x+e.y)+(e.z+e.w);
    if (t==0) sm += el;
    red[t] = sm; __syncthreads();
    for (int s=128;s>0;s>>=1){ if (t<s) red[t]+=red[t+s]; __syncthreads(); }
    const float inv = 1.f/red[0];
    e.x*=inv; e.y*=inv; e.z*=inv; e.w*=inv;
    ((float4*)row)[t] = e;
    if (t==0) row[1024] = el*inv;
}

// ---------------- zero small scratch ----------------
__global__ void zero_scratch_kernel()
{
    int idx = blockIdx.x*256 + threadIdx.x;
    if (idx < BH*Nn) g_patch[idx] = 0.f;
    if (idx < Bsz*KLD) g_keep[idx] = 0.f;
    if (idx < Nn) g_cnt[idx] = 0.f;
}

// ---------------- column sums per (b,h) ----------------
__global__ __launch_bounds__(256)
void colsum_kernel(const float* __restrict__ S)
{
    const int bh = blockIdx.x;
    const int i0 = blockIdx.y*129, i1 = min(i0+129, Nn);
    const float* Sb = S + (size_t)bh*SB;
    const int t = threadIdx.x;

    float4 acc = make_float4(0.f,0.f,0.f,0.f);
    float accl = 0.f;
    for (int i=i0;i<i1;i++){
        const float* row = Sb + (size_t)i*SLD;
        const float4 v = ((const float4*)row)[t];
        acc.x+=v.x; acc.y+=v.y; acc.z+=v.z; acc.w+=v.w;
        if (t==0) accl += row[1024];
    }
    float* base = &g_patch[bh*Nn];
    atomicAdd(&base[t*4+0], acc.x);
    atomicAdd(&base[t*4+1], acc.y);
    atomicAdd(&base[t*4+2], acc.z);
    atomicAdd(&base[t*4+3], acc.w);
    if (t==0) atomicAdd(&base[1024], accl);
}

// ---------------- combine patch means + exploration ----------------
__global__ __launch_bounds__(256)
void ucb_combine_kernel(const float* __restrict__ ucb_score, const int* __restrict__ counter)
{
    const int b = blockIdx.x, t = threadIdx.x;
    const float logc = logf((float)(*counter) + 1.0f);
    for (int jj=t; jj<Nn-1; jj+=256){
        const int j = jj + 1;
        float s = 0.f;
        #pragma unroll
        for (int h=0; h<Hh; h++){
            const float expl = sqrtf(logc / (ucb_score[h*Nn + j] + 1e-6f));
            s += g_patch[(b*Hh + h)*Nn + j] * (1.f/(float)Nn) + expl;
        }
        g_gucb[b*(Nn-1) + jj] = s * (1.f/(float)Hh);
    }
}

// ---------------- exact top-k (bitonic; ties -> lower index) ----------------
__global__ __launch_bounds__(512)
void topk_kernel()
{
    __shared__ float sv[1024];
    __shared__ int   si[1024];
    const int b = blockIdx.x, t = threadIdx.x;

    for (int j=t;j<1024;j+=512){ sv[j] = g_gucb[b*1024 + j]; si[j] = j; }
    __syncthreads();

    for (int k=2;k<=1024;k<<=1){
        for (int j=k>>1;j>0;j>>=1){
            for (int i=t;i<1024;i+=512){
                const int ixj = i ^ j;
                if (ixj > i){
                    float v1 = sv[i], v2 = sv[ixj];
                    int  i1 = si[i],  i2 = si[ixj];
                    const bool before = (v1 > v2) || (v1 == v2 && i1 < i2);
                    const bool dirDesc = ((i & k) == 0);
                    if (dirDesc ? (!before) : before){
                        sv[i]=v2; sv[ixj]=v1; si[i]=i2; si[ixj]=i1;
                    }
                }
            }
            __syncthreads();
        }
    }

    if (t < KSEL){
        const int tok = si[t] + 1;
        g_keep[b*KLD + tok] = 1.f;
        atomicAdd(&g_cnt[tok], 1.f);
    }
    if (t == 0) g_keep[b*KLD + 0] = 1.f;
}

// ---------------- score_delta ----------------
__global__ void score_delta_kernel(float* __restrict__ out2)
{
    int idx = blockIdx.x*256 + threadIdx.x;
    if (idx < Hh*Nn) out2[idx] = g_cnt[idx % Nn] * (1.f/(float)Bsz);
}

// =======================================================================
extern "C" void kernel_launch(void* const* d_in, const int* in_sizes, int n_in,
                              void* d_out, int out_size)
{
    const float* x       = (const float*)d_in[0];
    const float* ucbsc   = (const float*)d_in[1];
    const float* Wqkv    = (const float*)d_in[2];
    const float* Wproj   = (const float*)d_in[3];
    const float* bproj   = (const float*)d_in[4];
    const int*   counter = (const int*)d_in[5];
    const int*   enabled = (const int*)d_in[6];
    float* out = (float*)d_out;

    float *qkv, *S, *ctx;
    cudaGetSymbolAddress((void**)&qkv, g_qkv);
    cudaGetSymbolAddress((void**)&S,   g_S);
    cudaGetSymbolAddress((void**)&ctx, g_ctx);

    // 0) zero scratch (independent)
    zero_scratch_kernel<<<(BH*Nn + 255)/256, 256>>>();

    // 1) qkv = x @ W_qkv   [4100 x 2304 x 768]
    {
        dim3 grid(2304/128, (Bsz*Nn + 127)/128);
        mma_gemm_nn<false><<<grid, 256>>>(x, Wqkv, nullptr, qkv,
                                          Bsz*Nn, 3*Cc, Cc, Cc, 3*Cc, 3*Cc);
    }
    // 2) S = 0.125 * Q @ K^T  per (b,h)
    {
        dim3 grid((Nn+127)/128, (Nn+127)/128, BH);
        mma_gemm_qk<<<grid, 256>>>(qkv, S);
    }
    // 3) softmax rows
    softmax_kernel<<<BH*Nn, 256>>>(S);

    // 4) column sums, ucb combine, top-k
    { dim3 grid(BH, 8); colsum_kernel<<<grid, 256>>>(S); }
    ucb_combine_kernel<<<Bsz, 256>>>(ucbsc, counter);
    topk_kernel<<<Bsz, 512>>>();

    // 5) fused prune+renorm+context GEMM
    {
        dim3 grid(1, (Nn+127)/128, BH);
        mma_gemm_ctx<<<grid, 256>>>(S, qkv, ctx, counter, enabled);
    }
    // 6) out = ctx @ W_proj + b_proj
    {
        dim3 grid(768/128, (Bsz*Nn + 127)/128);
        mma_gemm_nn<true><<<grid, 256>>>(ctx, Wproj, bproj, out,
                                         Bsz*Nn, Cc, Cc, Cc, Cc, Cc);
    }
    // 7) score_delta
    if (out_size >= Bsz*Nn*Cc + Hh*Nn) {
        score_delta_kernel<<<(Hh*Nn + 255)/256, 256>>>(out + (size_t)Bsz*Nn*Cc);
    }
}

// round 13
// speedup vs baseline: 1.1171x; 1.1024x over previous
#include <cuda_runtime.h>
#include <math.h>
#include <stdint.h>

// ---------------- problem constants ----------------
#define Bsz 4
#define Nn  1025
#define Cc  768
#define Hh  12
#define Dh  64
#define BH  (Bsz*Hh)           // 48
#define SLD 1028               // padded row stride for S
#define KLD 1028               // padded row stride for keep mask
#define SB  ((size_t)Nn*SLD)
#define KSEL 256
#define TR  16                 // rows per softmax block

// ---------------- scratch (device globals; allocs forbidden) ----------------
__device__ float g_qkv[(size_t)Bsz*Nn*3*Cc];
__device__ float g_S  [(size_t)BH*Nn*SLD];
__device__ float g_ctx[(size_t)Bsz*Nn*Cc];
__device__ float g_patch[BH*Nn];
__device__ float g_gucb[Bsz*(Nn-1)];
__device__ float g_keep[Bsz*KLD];
__device__ float g_cnt[Nn];

// ---------------- tf32 helpers ----------------
__device__ __forceinline__ uint32_t f2tf(float x){
    uint32_t r; asm("cvt.rna.tf32.f32 %0, %1;" : "=r"(r) : "f"(x)); return r;
}
__device__ __forceinline__ uint4 f2tf4(const float4& v){
    return make_uint4(f2tf(v.x), f2tf(v.y), f2tf(v.z), f2tf(v.w));
}
__device__ __forceinline__ void mma8(float* d, const uint32_t* a, const uint32_t* b){
    asm volatile("mma.sync.aligned.m16n8k8.row.col.f32.tf32.tf32.f32 "
        "{%0,%1,%2,%3}, {%4,%5,%6,%7}, {%8,%9}, {%0,%1,%2,%3};"
        : "+f"(d[0]), "+f"(d[1]), "+f"(d[2]), "+f"(d[3])
        : "r"(a[0]), "r"(a[1]), "r"(a[2]), "r"(a[3]), "r"(b[0]), "r"(b[1]));
}

// =====================================================================
// mma_gemm_nn: C[M,N] = A[M,K] @ B[K,N] (+bias).  tf32 tensor cores.
// Block tile 128x128, BK=16, 8 warps (4m x 2n), warp tile 32m x 64n.
// A-shared is [m][k] (stride 20): STS.128 stores, conflict-free frag loads.
// =====================================================================
template<bool BIAS>
__global__ __launch_bounds__(256,1)
void mma_gemm_nn(const float* __restrict__ A, const float* __restrict__ B,
                 const float* __restrict__ bias, float* __restrict__ C,
                 int M, int N, int K, int lda, int ldb, int ldc)
{
    __shared__ uint32_t As[2][128][20];
    __shared__ uint32_t Bs[2][16][136];
    const int tid = threadIdx.x, lane = tid & 31, warp = tid >> 5;
    const int wm = warp & 3;
    const int wN = warp >> 2;
    const int m0 = blockIdx.y*128, n0 = blockIdx.x*128;

    const int ar = tid >> 2, ak = (tid & 3) << 2;
    const bool aok0 = (m0 + ar)      < M;
    const bool aok1 = (m0 + ar + 64) < M;
    const float* Ap0 = A + (size_t)(m0+ar)*lda + ak;
    const float* Ap1 = A + (size_t)(m0+ar+64)*lda + ak;
    const int bk = tid >> 5, bn = (tid & 31) << 2;
    const float* Bp0 = B + (size_t)bk*ldb + n0 + bn;
    const float* Bp1 = B + (size_t)(bk+8)*ldb + n0 + bn;

    const float4 z4 = make_float4(0.f,0.f,0.f,0.f);
    float4 a0 = aok0 ? *(const float4*)Ap0 : z4;
    float4 a1 = aok1 ? *(const float4*)Ap1 : z4;
    float4 b0 = *(const float4*)Bp0;
    float4 b1 = *(const float4*)Bp1;

    auto stA = [&](int buf, const float4& v0, const float4& v1){
        *(uint4*)&As[buf][ar   ][ak] = f2tf4(v0);
        *(uint4*)&As[buf][ar+64][ak] = f2tf4(v1);
    };
    auto stB = [&](int buf, const float4& v0, const float4& v1){
        *(uint4*)&Bs[buf][bk  ][bn] = f2tf4(v0);
        *(uint4*)&Bs[buf][bk+8][bn] = f2tf4(v1);
    };

    stA(0,a0,a1); stB(0,b0,b1); __syncthreads();

    float acc[2][8][4];
    #pragma unroll
    for (int i=0;i<2;i++)
        #pragma unroll
        for (int j=0;j<8;j++)
            #pragma unroll
            for (int q=0;q<4;q++) acc[i][j][q]=0.f;

    const int kq = lane & 3, rq = lane >> 2;
    const int nk = K >> 4;
    for (int t=0;t<nk;t++){
        const int cur = t & 1;
        if (t+1<nk){
            a0 = aok0 ? *(const float4*)(Ap0 + (t+1)*16) : z4;
            a1 = aok1 ? *(const float4*)(Ap1 + (t+1)*16) : z4;
            b0 = *(const float4*)(Bp0 + (size_t)(t+1)*16*ldb);
            b1 = *(const float4*)(Bp1 + (size_t)(t+1)*16*ldb);
        }
        #pragma unroll
        for (int ks=0;ks<2;ks++){
            const int kb = ks*8;
            uint32_t af[2][4], bf[8][2];
            #pragma unroll
            for (int mt=0;mt<2;mt++){
                const int r = wm*32 + mt*16 + rq;
                af[mt][0] = As[cur][r  ][kb+kq];
                af[mt][1] = As[cur][r+8][kb+kq];
                af[mt][2] = As[cur][r  ][kb+kq+4];
                af[mt][3] = As[cur][r+8][kb+kq+4];
            }
            #pragma unroll
            for (int nt=0;nt<8;nt++){
                const int c = wN*64 + nt*8 + rq;
                bf[nt][0] = Bs[cur][kb+kq  ][c];
                bf[nt][1] = Bs[cur][kb+kq+4][c];
            }
            #pragma unroll
            for (int mt=0;mt<2;mt++)
                #pragma unroll
                for (int nt=0;nt<8;nt++) mma8(acc[mt][nt], af[mt], bf[nt]);
        }
        if (t+1<nk){ const int nxt = cur^1; stA(nxt,a0,a1); stB(nxt,b0,b1); }
        __syncthreads();
    }

    #pragma unroll
    for (int mt=0;mt<2;mt++){
        const int r0 = m0 + wm*32 + mt*16 + rq;
        #pragma unroll
        for (int nt=0;nt<8;nt++){
            const int gc = n0 + wN*64 + nt*8 + kq*2;
            float bx=0.f, by=0.f;
            if (BIAS){ bx = bias[gc]; by = bias[gc+1]; }
            if (r0 < M){
                float2 v; v.x = acc[mt][nt][0]+bx; v.y = acc[mt][nt][1]+by;
                *(float2*)&C[(size_t)r0*ldc + gc] = v;
            }
            if (r0+8 < M){
                float2 v; v.x = acc[mt][nt][2]+bx; v.y = acc[mt][nt][3]+by;
                *(float2*)&C[(size_t)(r0+8)*ldc + gc] = v;
            }
        }
    }
}

// =====================================================================
// mma_gemm_qk: S[bh] = 0.125 * Q @ K^T.  Operand rows stride 3*Cc.
// Both tiles use [m][k] shared layout (stride 20).
// =====================================================================
__global__ __launch_bounds__(256,1)
void mma_gemm_qk(const float* __restrict__ QKV, float* __restrict__ S)
{
    const int bh = blockIdx.z, b = bh / Hh, h = bh % Hh;
    const float* Q  = QKV + (size_t)b*Nn*3*Cc + (size_t)h*Dh;
    const float* Km = Q + Cc;
    float* Cs = S + (size_t)bh * SB;

    __shared__ uint32_t As[2][128][20];
    __shared__ uint32_t Bs[2][128][20];
    const int tid = threadIdx.x, lane = tid & 31, warp = tid >> 5;
    const int wm = warp & 3, wN = warp >> 2;
    const int m0 = blockIdx.y*128, n0 = blockIdx.x*128;

    const int ar = tid >> 2, ak = (tid & 3) << 2;
    const bool aok0 = (m0 + ar)      < Nn;
    const bool aok1 = (m0 + ar + 64) < Nn;
    const bool bok0 = (n0 + ar)      < Nn;
    const bool bok1 = (n0 + ar + 64) < Nn;
    const float* Ap0 = Q  + (size_t)(m0+ar)*(3*Cc) + ak;
    const float* Ap1 = Q  + (size_t)(m0+ar+64)*(3*Cc) + ak;
    const float* Bp0 = Km + (size_t)(n0+ar)*(3*Cc) + ak;
    const float* Bp1 = Km + (size_t)(n0+ar+64)*(3*Cc) + ak;

    const float4 z4 = make_float4(0.f,0.f,0.f,0.f);
    float4 a0 = aok0 ? *(const float4*)Ap0 : z4;
    float4 a1 = aok1 ? *(const float4*)Ap1 : z4;
    float4 b0 = bok0 ? *(const float4*)Bp0 : z4;
    float4 b1 = bok1 ? *(const float4*)Bp1 : z4;

    auto stT = [&](uint32_t (*dst)[20], const float4& v0, const float4& v1){
        *(uint4*)&dst[ar   ][ak] = f2tf4(v0);
        *(uint4*)&dst[ar+64][ak] = f2tf4(v1);
    };

    stT(As[0],a0,a1); stT(Bs[0],b0,b1); __syncthreads();

    float acc[2][8][4];
    #pragma unroll
    for (int i=0;i<2;i++)
        #pragma unroll
        for (int j=0;j<8;j++)
            #pragma unroll
            for (int q=0;q<4;q++) acc[i][j][q]=0.f;

    const int kq = lane & 3, rq = lane >> 2;
    const int nk = Dh >> 4;   // 4
    for (int t=0;t<nk;t++){
        const int cur = t & 1;
        if (t+1<nk){
            a0 = aok0 ? *(const float4*)(Ap0 + (t+1)*16) : z4;
            a1 = aok1 ? *(const float4*)(Ap1 + (t+1)*16) : z4;
            b0 = bok0 ? *(const float4*)(Bp0 + (t+1)*16) : z4;
            b1 = bok1 ? *(const float4*)(Bp1 + (t+1)*16) : z4;
        }
        #pragma unroll
        for (int ks=0;ks<2;ks++){
            const int kb = ks*8;
            uint32_t af[2][4], bf[8][2];
            #pragma unroll
            for (int mt=0;mt<2;mt++){
                const int r = wm*32 + mt*16 + rq;
                af[mt][0] = As[cur][r  ][kb+kq];
                af[mt][1] = As[cur][r+8][kb+kq];
                af[mt][2] = As[cur][r  ][kb+kq+4];
                af[mt][3] = As[cur][r+8][kb+kq+4];
            }
            #pragma unroll
            for (int nt=0;nt<8;nt++){
                const int c = wN*64 + nt*8 + rq;
                bf[nt][0] = Bs[cur][c][kb+kq];
                bf[nt][1] = Bs[cur][c][kb+kq+4];
            }
            #pragma unroll
            for (int mt=0;mt<2;mt++)
                #pragma unroll
                for (int nt=0;nt<8;nt++) mma8(acc[mt][nt], af[mt], bf[nt]);
        }
        if (t+1<nk){ const int nxt = cur^1; stT(As[nxt],a0,a1); stT(Bs[nxt],b0,b1); }
        __syncthreads();
    }

    const float alpha = 0.125f;
    #pragma unroll
    for (int mt=0;mt<2;mt++){
        const int r0 = m0 + wm*32 + mt*16 + rq;
        #pragma unroll
        for (int nt=0;nt<8;nt++){
            const int gc = n0 + wN*64 + nt*8 + kq*2;
            if (r0 < Nn){
                if (gc+1 < Nn){
                    float2 v; v.x=acc[mt][nt][0]*alpha; v.y=acc[mt][nt][1]*alpha;
                    *(float2*)&Cs[(size_t)r0*SLD + gc] = v;
                } else if (gc < Nn) Cs[(size_t)r0*SLD + gc] = acc[mt][nt][0]*alpha;
            }
            if (r0+8 < Nn){
                if (gc+1 < Nn){
                    float2 v; v.x=acc[mt][nt][2]*alpha; v.y=acc[mt][nt][3]*alpha;
                    *(float2*)&Cs[(size_t)(r0+8)*SLD + gc] = v;
                } else if (gc < Nn) Cs[(size_t)(r0+8)*SLD + gc] = acc[mt][nt][2]*alpha;
            }
        }
    }
}

// =====================================================================
// mma_gemm_ctx: fused prune-mask + renorm + (pruned @ V).
// =====================================================================
__global__ __launch_bounds__(256,1)
void mma_gemm_ctx(const float* __restrict__ S, const float* __restrict__ QKV,
                  float* __restrict__ ctx, const int* __restrict__ counter,
                  const int* __restrict__ enabled)
{
    const int bh = blockIdx.z, b = bh / Hh, h = bh % Hh;
    const bool prune = ((*enabled) != 0) && ((*counter) > 50);
    const float* Sp = S + (size_t)bh*SB;
    const float* V  = QKV + (size_t)b*Nn*3*Cc + 2*(size_t)Cc + (size_t)h*Dh;
    const float* kp = g_keep + (size_t)b*KLD;
    float* Cp = ctx + (size_t)b*Nn*Cc + (size_t)h*Dh;

    __shared__ uint32_t As[2][128][20];
    __shared__ uint32_t Bs[2][16][72];
    __shared__ float zsh[128];

    const int tid = threadIdx.x, lane = tid & 31, warp = tid >> 5;
    const int wm = warp & 3, wN = warp >> 2;
    const int m0 = blockIdx.y*128;

    const int ar = tid >> 2, ak = (tid & 3) << 2;
    const int gm0 = m0 + ar, gm1 = m0 + ar + 64;
    const bool aok0 = gm0 < Nn, aok1 = gm1 < Nn;
    const float keep0 = (prune && aok0) ? kp[gm0] : 1.f;
    const float keep1 = (prune && aok1) ? kp[gm1] : 1.f;
    const float* Ap0 = Sp + (size_t)(aok0 ? gm0 : 0)*SLD;
    const float* Ap1 = Sp + (size_t)(aok1 ? gm1 : 0)*SLD;
    const int bk = tid >> 4, bn = (tid & 15) << 2;
    const float* Bp = V + (size_t)bk*(3*Cc) + bn;

    const float4 z4 = make_float4(0.f,0.f,0.f,0.f);
    float z0 = 0.f, z1 = 0.f;

    auto ldrow = [&](const float* rowp, float keepi, int k0, bool ok, float& zacc)->float4{
        float4 v = z4;
        if (ok){
            const int c = k0 + ak;
            if (c + 3 < Nn) v = *(const float4*)(rowp + c);
            else {
                if (c   < Nn) v.x = rowp[c];
                if (c+1 < Nn) v.y = rowp[c+1];
                if (c+2 < Nn) v.z = rowp[c+2];
                if (c+3 < Nn) v.w = rowp[c+3];
            }
            if (keepi < 0.5f){
                float4 kv = z4;
                if (c + 3 < Nn) kv = *(const float4*)(kp + c);
                else {
                    if (c   < Nn) kv.x = kp[c];
                    if (c+1 < Nn) kv.y = kp[c+1];
                    if (c+2 < Nn) kv.z = kp[c+2];
                    if (c+3 < Nn) kv.w = kp[c+3];
                }
                v.x*=kv.x; v.y*=kv.y; v.z*=kv.z; v.w*=kv.w;
            }
            zacc += (v.x+v.y)+(v.z+v.w);
        }
        return v;
    };
    auto ldB = [&](int k0)->float4{
        return (k0 + bk < Nn) ? *(const float4*)(Bp + (size_t)k0*(3*Cc)) : z4;
    };
    auto stA = [&](int buf, const float4& v0, const float4& v1){
        *(uint4*)&As[buf][ar   ][ak] = f2tf4(v0);
        *(uint4*)&As[buf][ar+64][ak] = f2tf4(v1);
    };
    auto stB = [&](int buf, const float4& v){
        *(uint4*)&Bs[buf][bk][bn] = f2tf4(v);
    };

    float4 a0 = ldrow(Ap0, keep0, 0, aok0, z0);
    float4 a1 = ldrow(Ap1, keep1, 0, aok1, z1);
    float4 bv = ldB(0);
    stA(0,a0,a1); stB(0,bv); __syncthreads();

    float acc[2][4][4];
    #pragma unroll
    for (int i=0;i<2;i++)
        #pragma unroll
        for (int j=0;j<4;j++)
            #pragma unroll
            for (int q=0;q<4;q++) acc[i][j][q]=0.f;

    const int kq = lane & 3, rq = lane >> 2;
    const int nk = (Nn + 15) >> 4;   // 65
    for (int t=0;t<nk;t++){
        const int cur = t & 1;
        if (t+1<nk){
            a0 = ldrow(Ap0, keep0, (t+1)*16, aok0, z0);
            a1 = ldrow(Ap1, keep1, (t+1)*16, aok1, z1);
            bv = ldB((t+1)*16);
        }
        #pragma unroll
        for (int ks=0;ks<2;ks++){
            const int kb = ks*8;
            uint32_t af[2][4], bf[4][2];
            #pragma unroll
            for (int mt=0;mt<2;mt++){
                const int r = wm*32 + mt*16 + rq;
                af[mt][0] = As[cur][r  ][kb+kq];
                af[mt][1] = As[cur][r+8][kb+kq];
                af[mt][2] = As[cur][r  ][kb+kq+4];
                af[mt][3] = As[cur][r+8][kb+kq+4];
            }
            #pragma unroll
            for (int nt=0;nt<4;nt++){
                const int c = wN*32 + nt*8 + rq;
                bf[nt][0] = Bs[cur][kb+kq  ][c];
                bf[nt][1] = Bs[cur][kb+kq+4][c];
            }
            #pragma unroll
            for (int mt=0;mt<2;mt++)
                #pragma unroll
                for (int nt=0;nt<4;nt++) mma8(acc[mt][nt], af[mt], bf[nt]);
        }
        if (t+1<nk){ const int nxt = cur^1; stA(nxt,a0,a1); stB(nxt,bv); }
        __syncthreads();
    }

    z0 += __shfl_xor_sync(0xffffffffu, z0, 1);
    z0 += __shfl_xor_sync(0xffffffffu, z0, 2);
    z1 += __shfl_xor_sync(0xffffffffu, z1, 1);
    z1 += __shfl_xor_sync(0xffffffffu, z1, 2);
    if ((lane & 3) == 0){ zsh[ar] = z0; zsh[ar+64] = z1; }
    __syncthreads();

    #pragma unroll
    for (int mt=0;mt<2;mt++){
        const int lr = wm*32 + mt*16 + rq;
        const int r0 = m0 + lr;
        const float iz0 = prune ? 1.f/(zsh[lr]   + 1e-8f) : 1.f;
        const float iz1 = prune ? 1.f/(zsh[lr+8] + 1e-8f) : 1.f;
        #pragma unroll
        for (int nt=0;nt<4;nt++){
            const int gc = wN*32 + nt*8 + kq*2;
            if (r0 < Nn){
                float2 v; v.x=acc[mt][nt][0]*iz0; v.y=acc[mt][nt][1]*iz0;
                *(float2*)&Cp[(size_t)r0*Cc + gc] = v;
            }
            if (r0+8 < Nn){
                float2 v; v.x=acc[mt][nt][2]*iz1; v.y=acc[mt][nt][3]*iz1;
                *(float2*)&Cp[(size_t)(r0+8)*Cc + gc] = v;
            }
        }
    }
}

// ---------------- fused softmax + column-sum ----------------
// grid (BH, ceil(Nn/TR)), 256 threads. Each block: TR rows of one (b,h).
// Column partial sums kept in registers; one atomicAdd set per block.
__global__ __launch_bounds__(256)
void softmax_colsum_kernel(float* __restrict__ S)
{
    const int bh = blockIdx.x;
    const int r0 = blockIdx.y * TR;
    float* Sb = S + (size_t)bh * SB;
    const int t = threadIdx.x, lane = t & 31, w = t >> 5;
    __shared__ float red[16];

    float4 cacc = make_float4(0.f,0.f,0.f,0.f);
    float caccL = 0.f;

    for (int rr = 0; rr < TR; rr++){
        const int r = r0 + rr;
        if (r >= Nn) break;
        float* row = Sb + (size_t)r * SLD;

        float4 v = ((const float4*)row)[t];
        const float last = row[1024];

        // block max
        float m4 = fmaxf(fmaxf(v.x,v.y), fmaxf(v.z,v.w));
        m4 = fmaxf(m4, last);
        #pragma unroll
        for (int s=16;s;s>>=1) m4 = fmaxf(m4, __shfl_xor_sync(0xffffffffu, m4, s));
        if (lane == 0) red[w] = m4;
        __syncthreads();
        float mx = red[0];
        #pragma unroll
        for (int q=1;q<8;q++) mx = fmaxf(mx, red[q]);

        // exp + block sum
        float4 e;
        e.x = __expf(v.x-mx); e.y = __expf(v.y-mx);
        e.z = __expf(v.z-mx); e.w = __expf(v.w-mx);
        const float el = __expf(last-mx);
        float sm = (e.x+e.y)+(e.z+e.w);
        if (t == 0) sm += el;
        #pragma unroll
        for (int s=16;s;s>>=1) sm += __shfl_xor_sync(0xffffffffu, sm, s);
        if (lane == 0) red[8+w] = sm;
        __syncthreads();
        float tot = red[8];
        #pragma unroll
        for (int q=1;q<8;q++) tot += red[8+q];
        const float inv = 1.f / tot;

        e.x*=inv; e.y*=inv; e.z*=inv; e.w*=inv;
        ((float4*)row)[t] = e;
        if (t == 0) row[1024] = el*inv;

        cacc.x += e.x; cacc.y += e.y; cacc.z += e.z; cacc.w += e.w;
        if (t == 0) caccL += el*inv;
        __syncthreads();   // protect red[] before next row
    }

    float* base = &g_patch[bh*Nn];
    atomicAdd(&base[t*4+0], cacc.x);
    atomicAdd(&base[t*4+1], cacc.y);
    atomicAdd(&base[t*4+2], cacc.z);
    atomicAdd(&base[t*4+3], cacc.w);
    if (t == 0) atomicAdd(&base[1024], caccL);
}

// ---------------- zero small scratch ----------------
__global__ void zero_scratch_kernel()
{
    int idx = blockIdx.x*256 + threadIdx.x;
    if (idx < BH*Nn) g_patch[idx] = 0.f;
    if (idx < Bsz*KLD) g_keep[idx] = 0.f;
    if (idx < Nn) g_cnt[idx] = 0.f;
}

// ---------------- combine patch means + exploration ----------------
__global__ __launch_bounds__(256)
void ucb_combine_kernel(const float* __restrict__ ucb_score, const int* __restrict__ counter)
{
    const int b = blockIdx.x, t = threadIdx.x;
    const float logc = logf((float)(*counter) + 1.0f);
    for (int jj=t; jj<Nn-1; jj+=256){
        const int j = jj + 1;
        float s = 0.f;
        #pragma unroll
        for (int h=0; h<Hh; h++){
            const float expl = sqrtf(logc / (ucb_score[h*Nn + j] + 1e-6f));
            s += g_patch[(b*Hh + h)*Nn + j] * (1.f/(float)Nn) + expl;
        }
        g_gucb[b*(Nn-1) + jj] = s * (1.f/(float)Hh);
    }
}

// ---------------- exact top-k (bitonic; ties -> lower index) ----------------
__global__ __launch_bounds__(512)
void topk_kernel()
{
    __shared__ float sv[1024];
    __shared__ int   si[1024];
    const int b = blockIdx.x, t = threadIdx.x;

    for (int j=t;j<1024;j+=512){ sv[j] = g_gucb[b*1024 + j]; si[j] = j; }
    __syncthreads();

    for (int k=2;k<=1024;k<<=1){
        for (int j=k>>1;j>0;j>>=1){
            for (int i=t;i<1024;i+=512){
                const int ixj = i ^ j;
                if (ixj > i){
                    float v1 = sv[i], v2 = sv[ixj];
                    int  i1 = si[i],  i2 = si[ixj];
                    const bool before = (v1 > v2) || (v1 == v2 && i1 < i2);
                    const bool dirDesc = ((i & k) == 0);
                    if (dirDesc ? (!before) : before){
                        sv[i]=v2; sv[ixj]=v1; si[i]=i2; si[ixj]=i1;
                    }
                }
            }
            __syncthreads();
        }
    }

    if (t < KSEL){
        const int tok = si[t] + 1;
        g_keep[b*KLD + tok] = 1.f;
        atomicAdd(&g_cnt[tok], 1.f);
    }
    if (t == 0) g_keep[b*KLD + 0] = 1.f;
}

// ---------------- score_delta ----------------
__global__ void score_delta_kernel(float* __restrict__ out2)
{
    int idx = blockIdx.x*256 + threadIdx.x;
    if (idx < Hh*Nn) out2[idx] = g_cnt[idx % Nn] * (1.f/(float)Bsz);
}

// =======================================================================
extern "C" void kernel_launch(void* const* d_in, const int* in_sizes, int n_in,
                              void* d_out, int out_size)
{
    const float* x       = (const float*)d_in[0];
    const float* ucbsc   = (const float*)d_in[1];
    const float* Wqkv    = (const float*)d_in[2];
    const float* Wproj   = (const float*)d_in[3];
    const float* bproj   = (const float*)d_in[4];
    const int*   counter = (const int*)d_in[5];
    const int*   enabled = (const int*)d_in[6];
    float* out = (float*)d_out;

    float *qkv, *S, *ctx;
    cudaGetSymbolAddress((void**)&qkv, g_qkv);
    cudaGetSymbolAddress((void**)&S,   g_S);
    cudaGetSymbolAddress((void**)&ctx, g_ctx);

    // 0) zero scratch
    zero_scratch_kernel<<<(BH*Nn + 255)/256, 256>>>();

    // 1) qkv = x @ W_qkv   [4100 x 2304 x 768]
    {
        dim3 grid(2304/128, (Bsz*Nn + 127)/128);
        mma_gemm_nn<false><<<grid, 256>>>(x, Wqkv, nullptr, qkv,
                                          Bsz*Nn, 3*Cc, Cc, Cc, 3*Cc, 3*Cc);
    }
    // 2) S = 0.125 * Q @ K^T  per (b,h)
    {
        dim3 grid((Nn+127)/128, (Nn+127)/128, BH);
        mma_gemm_qk<<<grid, 256>>>(qkv, S);
    }
    // 3) softmax + column sums (fused)
    {
        dim3 grid(BH, (Nn + TR - 1)/TR);
        softmax_colsum_kernel<<<grid, 256>>>(S);
    }
    // 4) ucb combine, top-k
    ucb_combine_kernel<<<Bsz, 256>>>(ucbsc, counter);
    topk_kernel<<<Bsz, 512>>>();

    // 5) fused prune+renorm+context GEMM
    {
        dim3 grid(1, (Nn+127)/128, BH);
        mma_gemm_ctx<<<grid, 256>>>(S, qkv, ctx, counter, enabled);
    }
    // 6) out = ctx @ W_proj + b_proj
    {
        dim3 grid(768/128, (Bsz*Nn + 127)/128);
        mma_gemm_nn<true><<<grid, 256>>>(ctx, Wproj, bproj, out,
                                         Bsz*Nn, Cc, Cc, Cc, Cc, Cc);
    }
    // 7) score_delta
    if (out_size >= Bsz*Nn*Cc + Hh*Nn) {
        score_delta_kernel<<<(Hh*Nn + 255)/256, 256>>>(out + (size_t)Bsz*Nn*Cc);
    }
}